// round 1
// baseline (speedup 1.0000x reference)
#include <cuda_runtime.h>
#include <math.h>

#define N_NODES 50000
#define N_EDGES 800000
#define IN_CH   128
#define HID_CH  256
#define OUT_CH  128

// ---------------- scratch (__device__ globals; no allocation allowed) ----------------
__device__ int   g_deg[N_NODES];
__device__ float g_dinv[N_NODES];
__device__ float g_t1[(size_t)N_NODES * IN_CH];   // aggregated scaled x   (25.6 MB)
__device__ float g_h [(size_t)N_NODES * HID_CH];  // relu hidden          (51.2 MB)
__device__ float g_p [(size_t)N_NODES * OUT_CH];  // h @ W2               (25.6 MB)

// ---------------- degree / dinv ----------------
__global__ void k_zero_deg() {
    int i = blockIdx.x * blockDim.x + threadIdx.x;
    if (i < N_NODES) g_deg[i] = 0;
}

__global__ void k_count_deg(const int* __restrict__ ei) {
    int i = blockIdx.x * blockDim.x + threadIdx.x;
    if (i < N_EDGES) atomicAdd(&g_deg[ei[N_EDGES + i]], 1);
}

__global__ void k_dinv() {
    int i = blockIdx.x * blockDim.x + threadIdx.x;
    if (i < N_NODES) g_dinv[i] = rsqrtf((float)g_deg[i] + 1.0f);
}

// ---------------- elementwise: out4[idx] = in4[idx] * dinv[row]  (C4 = 32 -> 128 ch) ----------------
__global__ void k_scale_rows(const float4* __restrict__ in, float4* __restrict__ out) {
    int idx = blockIdx.x * blockDim.x + threadIdx.x;
    if (idx >= N_NODES * 32) return;
    int row = idx >> 5;
    float s = g_dinv[row];
    float4 v = in[idx];
    v.x *= s; v.y *= s; v.z *= s; v.w *= s;
    out[idx] = v;
}

// ---------------- final epilogue: out = dinv[row]*out + b2[col] ----------------
__global__ void k_final(float4* __restrict__ out, const float4* __restrict__ b2) {
    int idx = blockIdx.x * blockDim.x + threadIdx.x;
    if (idx >= N_NODES * 32) return;
    int row = idx >> 5;
    float s = g_dinv[row];
    float4 v = out[idx];
    float4 b = b2[idx & 31];
    v.x = fmaf(v.x, s, b.x);
    v.y = fmaf(v.y, s, b.y);
    v.z = fmaf(v.z, s, b.z);
    v.w = fmaf(v.w, s, b.w);
    out[idx] = v;
}

// ---------------- edge scatter: acc[dst] += dinv[src] * feat[src], 128 channels ----------------
// One warp per edge; lane handles one float4 (32 x float4 = 128 floats).
__global__ void __launch_bounds__(256) k_edge_scatter(
    const float* __restrict__ feat, const int* __restrict__ ei,
    float* __restrict__ acc)
{
    int gw = (blockIdx.x * blockDim.x + threadIdx.x) >> 5;
    if (gw >= N_EDGES) return;
    int lane = threadIdx.x & 31;
    int src = __ldg(ei + gw);
    int dst = __ldg(ei + N_EDGES + gw);
    float w = g_dinv[src];
    float4 v = *(const float4*)(feat + (size_t)src * 128 + lane * 4);
    v.x *= w; v.y *= w; v.z *= w; v.w *= w;
    float* a = acc + (size_t)dst * 128 + lane * 4;
    asm volatile("red.global.add.v4.f32 [%0], {%1, %2, %3, %4};"
                 :: "l"(a), "f"(v.x), "f"(v.y), "f"(v.z), "f"(v.w) : "memory");
}

// ---------------- fp32 GEMM: C[M,N] = op(A[M,K]) @ B[K,N] (+bias)(+relu) ----------------
// 64x64 block tile, BK=32, 256 threads, 4x4 microtile.
// SCALE: A row i scaled by g_dinv[i] at load time.
template<int BK, bool RELU, bool BIAS, bool SCALE>
__global__ void __launch_bounds__(256) k_gemm64(
    const float* __restrict__ A, const float* __restrict__ B,
    const float* __restrict__ bias, float* __restrict__ C,
    int M, int N, int K)
{
    const int BM = 64, BN = 64;
    __shared__ float As[BK][BM];
    __shared__ float Bs[BK][BN];

    int tid = threadIdx.x;
    int bm = blockIdx.y * BM;
    int bn = blockIdx.x * BN;
    int tx = tid & 15;   // 16 col groups * 4 = 64
    int ty = tid >> 4;   // 16 row groups * 4 = 64

    float acc[4][4] = {};

    int a_c4 = tid & 7;      // 8 float4 per A row (BK=32)
    int a_r  = tid >> 3;     // 0..31, two passes
    int b_c4 = tid & 15;     // 16 float4 per B row (BN=64)
    int b_r  = tid >> 4;     // 0..15, BK/16 passes

    for (int k0 = 0; k0 < K; k0 += BK) {
        // load A tile (transposed into smem), optional row scale, M-edge guarded
        #pragma unroll
        for (int p = 0; p < 2; p++) {
            int r = a_r + p * 32;
            int grow = bm + r;
            float4 v = make_float4(0.f, 0.f, 0.f, 0.f);
            if (grow < M) {
                v = *(const float4*)(A + (size_t)grow * K + k0 + a_c4 * 4);
                if (SCALE) {
                    float s = g_dinv[grow];
                    v.x *= s; v.y *= s; v.z *= s; v.w *= s;
                }
            }
            As[a_c4 * 4 + 0][r] = v.x;
            As[a_c4 * 4 + 1][r] = v.y;
            As[a_c4 * 4 + 2][r] = v.z;
            As[a_c4 * 4 + 3][r] = v.w;
        }
        // load B tile (K,N row-major; K,N always multiples of tile)
        #pragma unroll
        for (int p = 0; p < BK / 16; p++) {
            int r = b_r + p * 16;
            *(float4*)&Bs[r][b_c4 * 4] =
                *(const float4*)(B + (size_t)(k0 + r) * N + bn + b_c4 * 4);
        }
        __syncthreads();

        #pragma unroll
        for (int k = 0; k < BK; k++) {
            float4 a4 = *(float4*)&As[k][ty * 4];
            float4 b4 = *(float4*)&Bs[k][tx * 4];
            float ar[4] = {a4.x, a4.y, a4.z, a4.w};
            float br[4] = {b4.x, b4.y, b4.z, b4.w};
            #pragma unroll
            for (int i = 0; i < 4; i++)
                #pragma unroll
                for (int j = 0; j < 4; j++)
                    acc[i][j] = fmaf(ar[i], br[j], acc[i][j]);
        }
        __syncthreads();
    }

    // epilogue
    float4 bb = make_float4(0.f, 0.f, 0.f, 0.f);
    if (BIAS) bb = *(const float4*)(bias + bn + tx * 4);
    #pragma unroll
    for (int i = 0; i < 4; i++) {
        int grow = bm + ty * 4 + i;
        if (grow >= M) continue;
        float4 c;
        c.x = acc[i][0] + bb.x;
        c.y = acc[i][1] + bb.y;
        c.z = acc[i][2] + bb.z;
        c.w = acc[i][3] + bb.w;
        if (RELU) {
            c.x = fmaxf(c.x, 0.f); c.y = fmaxf(c.y, 0.f);
            c.z = fmaxf(c.z, 0.f); c.w = fmaxf(c.w, 0.f);
        }
        *(float4*)(C + (size_t)grow * N + bn + tx * 4) = c;
    }
}

// ---------------- launch ----------------
extern "C" void kernel_launch(void* const* d_in, const int* in_sizes, int n_in,
                              void* d_out, int out_size)
{
    const float* x  = (const float*)d_in[0];
    const int*   ei = (const int*)  d_in[1];
    const float* W1 = (const float*)d_in[2];
    const float* b1 = (const float*)d_in[3];
    const float* W2 = (const float*)d_in[4];
    const float* b2 = (const float*)d_in[5];
    float* out = (float*)d_out;

    void *p_t1, *p_h, *p_p;
    cudaGetSymbolAddress(&p_t1, g_t1);
    cudaGetSymbolAddress(&p_h,  g_h);
    cudaGetSymbolAddress(&p_p,  g_p);
    float* t1 = (float*)p_t1;
    float* h  = (float*)p_h;
    float* p  = (float*)p_p;

    const int T = 256;

    // degree + dinv (deterministic recompute every call)
    k_zero_deg<<<(N_NODES + T - 1) / T, T>>>();
    k_count_deg<<<(N_EDGES + T - 1) / T, T>>>(ei);
    k_dinv<<<(N_NODES + T - 1) / T, T>>>();

    int nvec = N_NODES * 32;                       // float4 count for 128-ch tensors
    int vgrid = (nvec + T - 1) / T;
    int egrid = (N_EDGES * 32 + T - 1) / T;        // one warp per edge

    // ---- layer 1: aggregate x, then GEMM ----
    // t1[i] = dinv[i]*x[i]  (self-loop init)
    k_scale_rows<<<vgrid, T>>>((const float4*)x, (float4*)t1);
    // t1[dst] += dinv[src]*x[src]
    k_edge_scatter<<<egrid, T>>>(x, ei, t1);
    // h = relu( (dinv .* t1) @ W1 + b1 )
    {
        dim3 grid(HID_CH / 64, (N_NODES + 63) / 64);
        k_gemm64<32, true, true, true><<<grid, 256>>>(t1, W1, b1, h, N_NODES, HID_CH, IN_CH);
    }

    // ---- layer 2: GEMM, then aggregate ----
    // p = h @ W2   (bias deferred past aggregation)
    {
        dim3 grid(OUT_CH / 64, (N_NODES + 63) / 64);
        k_gemm64<32, false, false, false><<<grid, 256>>>(h, W2, nullptr, p, N_NODES, OUT_CH, HID_CH);
    }
    // out[i] = dinv[i]*p[i]  (self-loop init)
    k_scale_rows<<<vgrid, T>>>((const float4*)p, (float4*)out);
    // out[dst] += dinv[src]*p[src]
    k_edge_scatter<<<egrid, T>>>(p, ei, out);
    // out = dinv[i]*out + b2
    k_final<<<vgrid, T>>>((float4*)out, (const float4*)b2);
}

// round 5
// speedup vs baseline: 1.2018x; 1.2018x over previous
#include <cuda_runtime.h>
#include <math.h>

#define N_NODES 50000
#define N_EDGES 800000
#define IN_CH   128
#define HID_CH  256
#define OUT_CH  128

// ---------------- scratch (__device__ globals; no allocation allowed) ----------------
__device__ int   g_deg[N_NODES];
__device__ float g_dinv[N_NODES];
__device__ int   g_rowstart[N_NODES + 1];
__device__ int   g_fill[N_NODES];
__device__ int   g_csr[N_EDGES];
__device__ float g_t1[(size_t)N_NODES * IN_CH];   // aggregated scaled x
__device__ float g_h [(size_t)N_NODES * HID_CH];  // relu hidden
__device__ float g_p [(size_t)N_NODES * OUT_CH];  // h @ W2

// ---------------- degree / CSR build ----------------
__global__ void k_zero_deg() {
    int i = blockIdx.x * blockDim.x + threadIdx.x;
    if (i < N_NODES) g_deg[i] = 0;
}

__global__ void k_count_deg(const int* __restrict__ ei) {
    int i = blockIdx.x * blockDim.x + threadIdx.x;
    if (i < N_EDGES) atomicAdd(&g_deg[ei[N_EDGES + i]], 1);
}

// single block, 1024 threads: exclusive prefix sum of deg -> rowstart & fill,
// plus dinv = rsqrt(deg+1)
__global__ void k_scan() {
    __shared__ int wsum[32];
    __shared__ int s_carry;
    int tid = threadIdx.x, lane = tid & 31, wid = tid >> 5;
    if (tid == 0) s_carry = 0;
    __syncthreads();
    for (int base = 0; base < N_NODES; base += 1024) {
        int i = base + tid;
        int d = (i < N_NODES) ? g_deg[i] : 0;
        int v = d;
        #pragma unroll
        for (int o = 1; o < 32; o <<= 1) {
            int t = __shfl_up_sync(0xffffffffu, v, o);
            if (lane >= o) v += t;
        }
        if (lane == 31) wsum[wid] = v;
        __syncthreads();
        if (wid == 0) {
            int w = wsum[lane];
            #pragma unroll
            for (int o = 1; o < 32; o <<= 1) {
                int t = __shfl_up_sync(0xffffffffu, w, o);
                if (lane >= o) w += t;
            }
            wsum[lane] = w;
        }
        __syncthreads();
        int carry = s_carry;
        int excl = carry + (wid ? wsum[wid - 1] : 0) + v - d;
        if (i < N_NODES) {
            g_rowstart[i] = excl;
            g_fill[i]     = excl;
            g_dinv[i]     = rsqrtf((float)d + 1.0f);
        }
        __syncthreads();
        if (tid == 1023) s_carry = carry + wsum[31];
        __syncthreads();
    }
    if (threadIdx.x == 0) g_rowstart[N_NODES] = N_EDGES;
}

__global__ void k_fill_csr(const int* __restrict__ ei) {
    int i = blockIdx.x * blockDim.x + threadIdx.x;
    if (i < N_EDGES) {
        int src = ei[i];
        int dst = ei[N_EDGES + i];
        int pos = atomicAdd(&g_fill[dst], 1);
        g_csr[pos] = src;
    }
}

// ---------------- gather aggregation: one warp per node, 128 channels ----------------
// out[n] = dinv[n]*feat[n] + sum_{s in csr[n]} dinv[s]*feat[s]
// FINAL:  out[n] = dinv[n]*(that) + b2
template<bool FINAL>
__global__ void __launch_bounds__(256) k_agg(
    const float* __restrict__ feat, float* __restrict__ outp,
    const float* __restrict__ bias)
{
    int n = (blockIdx.x * blockDim.x + threadIdx.x) >> 5;
    if (n >= N_NODES) return;
    int lane = threadIdx.x & 31;
    int start = g_rowstart[n];
    int end   = g_rowstart[n + 1];
    float dn = g_dinv[n];
    float4 self = *(const float4*)(feat + (size_t)n * 128 + lane * 4);
    float4 acc;
    acc.x = dn * self.x; acc.y = dn * self.y;
    acc.z = dn * self.z; acc.w = dn * self.w;

    for (int r = start; r < end; r += 32) {
        int ne = min(32, end - r);
        int s = 0; float w = 0.f;
        if (lane < ne) { s = g_csr[r + lane]; w = g_dinv[s]; }
        for (int j = 0; j < ne; j++) {
            int   sj = __shfl_sync(0xffffffffu, s, j);
            float wj = __shfl_sync(0xffffffffu, w, j);
            float4 v = *(const float4*)(feat + (size_t)sj * 128 + lane * 4);
            acc.x = fmaf(wj, v.x, acc.x);
            acc.y = fmaf(wj, v.y, acc.y);
            acc.z = fmaf(wj, v.z, acc.z);
            acc.w = fmaf(wj, v.w, acc.w);
        }
    }
    if (FINAL) {
        float4 b = *(const float4*)(bias + lane * 4);
        acc.x = fmaf(dn, acc.x, b.x);
        acc.y = fmaf(dn, acc.y, b.y);
        acc.z = fmaf(dn, acc.z, b.z);
        acc.w = fmaf(dn, acc.w, b.w);
    }
    *(float4*)(outp + (size_t)n * 128 + lane * 4) = acc;
}

// ---------------- fp32 GEMM (round-1 verbatim, known good) ----------------
// 64x64 block tile, BK=32, 256 threads, 4x4 microtile.
// SCALE: A row i scaled by g_dinv[i] at load time.
template<int BK, bool RELU, bool BIAS, bool SCALE>
__global__ void __launch_bounds__(256) k_gemm64(
    const float* __restrict__ A, const float* __restrict__ B,
    const float* __restrict__ bias, float* __restrict__ C,
    int M, int N, int K)
{
    const int BM = 64, BN = 64;
    __shared__ float As[BK][BM];
    __shared__ float Bs[BK][BN];

    int tid = threadIdx.x;
    int bm = blockIdx.y * BM;
    int bn = blockIdx.x * BN;
    int tx = tid & 15;   // 16 col groups * 4 = 64
    int ty = tid >> 4;   // 16 row groups * 4 = 64

    float acc[4][4] = {};

    int a_c4 = tid & 7;      // 8 float4 per A row (BK=32)
    int a_r  = tid >> 3;     // 0..31, two passes
    int b_c4 = tid & 15;     // 16 float4 per B row (BN=64)
    int b_r  = tid >> 4;     // 0..15, BK/16 passes

    for (int k0 = 0; k0 < K; k0 += BK) {
        #pragma unroll
        for (int p = 0; p < 2; p++) {
            int r = a_r + p * 32;
            int grow = bm + r;
            float4 v = make_float4(0.f, 0.f, 0.f, 0.f);
            if (grow < M) {
                v = *(const float4*)(A + (size_t)grow * K + k0 + a_c4 * 4);
                if (SCALE) {
                    float s = g_dinv[grow];
                    v.x *= s; v.y *= s; v.z *= s; v.w *= s;
                }
            }
            As[a_c4 * 4 + 0][r] = v.x;
            As[a_c4 * 4 + 1][r] = v.y;
            As[a_c4 * 4 + 2][r] = v.z;
            As[a_c4 * 4 + 3][r] = v.w;
        }
        #pragma unroll
        for (int p = 0; p < BK / 16; p++) {
            int r = b_r + p * 16;
            *(float4*)&Bs[r][b_c4 * 4] =
                *(const float4*)(B + (size_t)(k0 + r) * N + bn + b_c4 * 4);
        }
        __syncthreads();

        #pragma unroll
        for (int k = 0; k < BK; k++) {
            float4 a4 = *(float4*)&As[k][ty * 4];
            float4 b4 = *(float4*)&Bs[k][tx * 4];
            float ar[4] = {a4.x, a4.y, a4.z, a4.w};
            float br[4] = {b4.x, b4.y, b4.z, b4.w};
            #pragma unroll
            for (int i = 0; i < 4; i++)
                #pragma unroll
                for (int j = 0; j < 4; j++)
                    acc[i][j] = fmaf(ar[i], br[j], acc[i][j]);
        }
        __syncthreads();
    }

    float4 bb = make_float4(0.f, 0.f, 0.f, 0.f);
    if (BIAS) bb = *(const float4*)(bias + bn + tx * 4);
    #pragma unroll
    for (int i = 0; i < 4; i++) {
        int grow = bm + ty * 4 + i;
        if (grow >= M) continue;
        float4 c;
        c.x = acc[i][0] + bb.x;
        c.y = acc[i][1] + bb.y;
        c.z = acc[i][2] + bb.z;
        c.w = acc[i][3] + bb.w;
        if (RELU) {
            c.x = fmaxf(c.x, 0.f); c.y = fmaxf(c.y, 0.f);
            c.z = fmaxf(c.z, 0.f); c.w = fmaxf(c.w, 0.f);
        }
        *(float4*)(C + (size_t)grow * N + bn + tx * 4) = c;
    }
}

// ---------------- launch ----------------
extern "C" void kernel_launch(void* const* d_in, const int* in_sizes, int n_in,
                              void* d_out, int out_size)
{
    const float* x  = (const float*)d_in[0];
    const int*   ei = (const int*)  d_in[1];
    const float* W1 = (const float*)d_in[2];
    const float* b1 = (const float*)d_in[3];
    const float* W2 = (const float*)d_in[4];
    const float* b2 = (const float*)d_in[5];
    float* out = (float*)d_out;

    void *p_t1, *p_h, *p_p;
    cudaGetSymbolAddress(&p_t1, g_t1);
    cudaGetSymbolAddress(&p_h,  g_h);
    cudaGetSymbolAddress(&p_p,  g_p);
    float* t1 = (float*)p_t1;
    float* h  = (float*)p_h;
    float* p  = (float*)p_p;

    const int T = 256;

    // CSR build (recomputed every call, deterministic work)
    k_zero_deg<<<(N_NODES + T - 1) / T, T>>>();
    k_count_deg<<<(N_EDGES + T - 1) / T, T>>>(ei);
    k_scan<<<1, 1024>>>();
    k_fill_csr<<<(N_EDGES + T - 1) / T, T>>>(ei);

    int agrid = (N_NODES * 32 + T - 1) / T;   // one warp per node

    // ---- layer 1: aggregate x (gather), then GEMM with fused dinv row-scale ----
    k_agg<false><<<agrid, T>>>(x, t1, nullptr);
    {
        dim3 grid(HID_CH / 64, (N_NODES + 63) / 64);
        k_gemm64<32, true, true, true><<<grid, 256>>>(t1, W1, b1, h, N_NODES, HID_CH, IN_CH);
    }

    // ---- layer 2: GEMM, then aggregate (gather) with fused final scale + bias ----
    {
        dim3 grid(OUT_CH / 64, (N_NODES + 63) / 64);
        k_gemm64<32, false, false, false><<<grid, 256>>>(h, W2, nullptr, p, N_NODES, OUT_CH, HID_CH);
    }
    k_agg<true><<<agrid, T>>>(p, out, b2);
}

// round 10
// speedup vs baseline: 1.8277x; 1.5208x over previous
#include <cuda_runtime.h>
#include <cuda_bf16.h>
#include <math.h>
#include <cstdint>

#define N_NODES 50000
#define N_EDGES 800000
#define IN_CH   128
#define HID_CH  256
#define OUT_CH  128

// ---------------- scratch (__device__ globals; no allocation allowed) ----------------
__device__ int   g_deg[N_NODES];
__device__ float g_dinv[N_NODES];
__device__ int   g_rowstart[N_NODES + 1];
__device__ int   g_fill[N_NODES];
__device__ int   g_csr[N_EDGES];
__device__ float g_p[(size_t)N_NODES * OUT_CH];              // h @ W2 (fp32)
// bf16 hi/lo split feature buffers
__device__ __nv_bfloat16 g_ahi[(size_t)N_NODES * IN_CH];     // layer-1 A (aggregated, dinv-scaled)
__device__ __nv_bfloat16 g_alo[(size_t)N_NODES * IN_CH];
__device__ __nv_bfloat16 g_hhi[(size_t)N_NODES * HID_CH];    // relu hidden
__device__ __nv_bfloat16 g_hlo[(size_t)N_NODES * HID_CH];
// transposed + split weights: Wt[n][k]
__device__ __nv_bfloat16 g_w1h[HID_CH * IN_CH];
__device__ __nv_bfloat16 g_w1l[HID_CH * IN_CH];
__device__ __nv_bfloat16 g_w2h[OUT_CH * HID_CH];
__device__ __nv_bfloat16 g_w2l[OUT_CH * HID_CH];

// ---------------- helpers ----------------
__device__ __forceinline__ uint32_t smem_u32(const void* p) {
    uint32_t a;
    asm("{ .reg .u64 t; cvta.to.shared.u64 t, %1; cvt.u32.u64 %0, t; }" : "=r"(a) : "l"(p));
    return a;
}
__device__ __forceinline__ void ldsm4(uint32_t* r, uint32_t addr) {
    asm volatile("ldmatrix.sync.aligned.m8n8.x4.shared.b16 {%0,%1,%2,%3}, [%4];"
        : "=r"(r[0]), "=r"(r[1]), "=r"(r[2]), "=r"(r[3]) : "r"(addr));
}
__device__ __forceinline__ void mma16816(float* c, const uint32_t* a, uint32_t b0, uint32_t b1) {
    asm volatile("mma.sync.aligned.m16n8k16.row.col.f32.bf16.bf16.f32 "
        "{%0,%1,%2,%3}, {%4,%5,%6,%7}, {%8,%9}, {%0,%1,%2,%3};"
        : "+f"(c[0]), "+f"(c[1]), "+f"(c[2]), "+f"(c[3])
        : "r"(a[0]), "r"(a[1]), "r"(a[2]), "r"(a[3]), "r"(b0), "r"(b1));
}

// ---------------- degree / CSR build (R5 verbatim, known good) ----------------
__global__ void k_zero_deg() {
    int i = blockIdx.x * blockDim.x + threadIdx.x;
    if (i < N_NODES) g_deg[i] = 0;
}

__global__ void k_count_deg(const int* __restrict__ ei) {
    int i = blockIdx.x * blockDim.x + threadIdx.x;
    if (i < N_EDGES) atomicAdd(&g_deg[ei[N_EDGES + i]], 1);
}

__global__ void k_scan() {
    __shared__ int wsum[32];
    __shared__ int s_carry;
    int tid = threadIdx.x, lane = tid & 31, wid = tid >> 5;
    if (tid == 0) s_carry = 0;
    __syncthreads();
    for (int base = 0; base < N_NODES; base += 1024) {
        int i = base + tid;
        int d = (i < N_NODES) ? g_deg[i] : 0;
        int v = d;
        #pragma unroll
        for (int o = 1; o < 32; o <<= 1) {
            int t = __shfl_up_sync(0xffffffffu, v, o);
            if (lane >= o) v += t;
        }
        if (lane == 31) wsum[wid] = v;
        __syncthreads();
        if (wid == 0) {
            int w = wsum[lane];
            #pragma unroll
            for (int o = 1; o < 32; o <<= 1) {
                int t = __shfl_up_sync(0xffffffffu, w, o);
                if (lane >= o) w += t;
            }
            wsum[lane] = w;
        }
        __syncthreads();
        int carry = s_carry;
        int excl = carry + (wid ? wsum[wid - 1] : 0) + v - d;
        if (i < N_NODES) {
            g_rowstart[i] = excl;
            g_fill[i]     = excl;
            g_dinv[i]     = rsqrtf((float)d + 1.0f);
        }
        __syncthreads();
        if (tid == 1023) s_carry = carry + wsum[31];
        __syncthreads();
    }
    if (threadIdx.x == 0) g_rowstart[N_NODES] = N_EDGES;
}

__global__ void k_fill_csr(const int* __restrict__ ei) {
    int i = blockIdx.x * blockDim.x + threadIdx.x;
    if (i < N_EDGES) {
        int src = ei[i];
        int dst = ei[N_EDGES + i];
        int pos = atomicAdd(&g_fill[dst], 1);
        g_csr[pos] = src;
    }
}

// ---------------- gather aggregation, fp32 out (R5 verbatim, known good) ----------------
template<bool FINAL>
__global__ void __launch_bounds__(256) k_agg(
    const float* __restrict__ feat, float* __restrict__ outp,
    const float* __restrict__ bias)
{
    int n = (blockIdx.x * blockDim.x + threadIdx.x) >> 5;
    if (n >= N_NODES) return;
    int lane = threadIdx.x & 31;
    int start = g_rowstart[n];
    int end   = g_rowstart[n + 1];
    float dn = g_dinv[n];
    float4 self = *(const float4*)(feat + (size_t)n * 128 + lane * 4);
    float4 acc;
    acc.x = dn * self.x; acc.y = dn * self.y;
    acc.z = dn * self.z; acc.w = dn * self.w;

    for (int r = start; r < end; r += 32) {
        int ne = min(32, end - r);
        int s = 0; float w = 0.f;
        if (lane < ne) { s = g_csr[r + lane]; w = g_dinv[s]; }
        for (int j = 0; j < ne; j++) {
            int   sj = __shfl_sync(0xffffffffu, s, j);
            float wj = __shfl_sync(0xffffffffu, w, j);
            float4 v = *(const float4*)(feat + (size_t)sj * 128 + lane * 4);
            acc.x = fmaf(wj, v.x, acc.x);
            acc.y = fmaf(wj, v.y, acc.y);
            acc.z = fmaf(wj, v.z, acc.z);
            acc.w = fmaf(wj, v.w, acc.w);
        }
    }
    if (FINAL) {
        float4 b = *(const float4*)(bias + lane * 4);
        acc.x = fmaf(dn, acc.x, b.x);
        acc.y = fmaf(dn, acc.y, b.y);
        acc.z = fmaf(dn, acc.z, b.z);
        acc.w = fmaf(dn, acc.w, b.w);
    }
    *(float4*)(outp + (size_t)n * 128 + lane * 4) = acc;
}

// ---------------- layer-1 aggregation, bf16 hi/lo out with fused outer dinv ----------------
// row = dinv[n]*(dinv[n]*x[n] + sum dinv[s]*x[s]) split into bf16 hi+lo
__global__ void __launch_bounds__(256) k_agg_bf16(
    const float* __restrict__ feat,
    __nv_bfloat16* __restrict__ ohi, __nv_bfloat16* __restrict__ olo)
{
    int n = (blockIdx.x * blockDim.x + threadIdx.x) >> 5;
    if (n >= N_NODES) return;
    int lane = threadIdx.x & 31;
    int start = g_rowstart[n];
    int end   = g_rowstart[n + 1];
    float dn = g_dinv[n];
    float4 self = *(const float4*)(feat + (size_t)n * 128 + lane * 4);
    float4 acc;
    acc.x = dn * self.x; acc.y = dn * self.y;
    acc.z = dn * self.z; acc.w = dn * self.w;

    for (int r = start; r < end; r += 32) {
        int ne = min(32, end - r);
        int s = 0; float w = 0.f;
        if (lane < ne) { s = g_csr[r + lane]; w = g_dinv[s]; }
        for (int j = 0; j < ne; j++) {
            int   sj = __shfl_sync(0xffffffffu, s, j);
            float wj = __shfl_sync(0xffffffffu, w, j);
            float4 v = *(const float4*)(feat + (size_t)sj * 128 + lane * 4);
            acc.x = fmaf(wj, v.x, acc.x);
            acc.y = fmaf(wj, v.y, acc.y);
            acc.z = fmaf(wj, v.z, acc.z);
            acc.w = fmaf(wj, v.w, acc.w);
        }
    }
    acc.x *= dn; acc.y *= dn; acc.z *= dn; acc.w *= dn;

    float f[4] = {acc.x, acc.y, acc.z, acc.w};
    __nv_bfloat16 hi[4], lo[4];
    #pragma unroll
    for (int j = 0; j < 4; j++) {
        hi[j] = __float2bfloat16(f[j]);
        lo[j] = __float2bfloat16(f[j] - __bfloat162float(hi[j]));
    }
    size_t o = (size_t)n * 128 + lane * 4;
    __nv_bfloat162 h0; h0.x = hi[0]; h0.y = hi[1];
    __nv_bfloat162 h1; h1.x = hi[2]; h1.y = hi[3];
    __nv_bfloat162 l0; l0.x = lo[0]; l0.y = lo[1];
    __nv_bfloat162 l1; l1.x = lo[2]; l1.y = lo[3];
    *(__nv_bfloat162*)(ohi + o)     = h0;
    *(__nv_bfloat162*)(ohi + o + 2) = h1;
    *(__nv_bfloat162*)(olo + o)     = l0;
    *(__nv_bfloat162*)(olo + o + 2) = l1;
}

// ---------------- weight prep: fp32 W[K][N] -> transposed Wt[n][k] bf16 hi/lo ----------------
__global__ void k_prep_w(const float* __restrict__ W1, const float* __restrict__ W2) {
    int idx = blockIdx.x * blockDim.x + threadIdx.x;
    if (idx >= 2 * 32768) return;
    int which = idx >> 15;
    int e = idx & 32767;
    if (which == 0) {
        int n = e & 255, k = e >> 8;            // n < 256, k < 128
        float w = W1[k * 256 + n];
        __nv_bfloat16 hi = __float2bfloat16(w);
        __nv_bfloat16 lo = __float2bfloat16(w - __bfloat162float(hi));
        g_w1h[n * 128 + k] = hi;
        g_w1l[n * 128 + k] = lo;
    } else {
        int n = e & 127, k = e >> 7;            // n < 128, k < 256
        float w = W2[k * 128 + n];
        __nv_bfloat16 hi = __float2bfloat16(w);
        __nv_bfloat16 lo = __float2bfloat16(w - __bfloat162float(hi));
        g_w2h[n * 256 + k] = hi;
        g_w2l[n * 256 + k] = lo;
    }
}

// ---------------- bf16 mma.sync GEMM: C[M,N] = Ahi@W + Alo@Whi (+bias)(+relu) ----------------
// CTA 256 thr (8 warps, 4Mx2N), tile 128x128, BK=64, warp tile m32 x n64.
// A row-major [M][K] bf16 hi/lo; W pre-transposed [N][K] bf16 hi/lo.
// SMEM tiles [128][64] bf16 with 16B-chunk XOR swizzle (chunk c -> c ^ (row&7)).
template<int N, int K, bool OUTBF16, bool RELU, bool BIAS>
__global__ void __launch_bounds__(256) k_mma(
    const __nv_bfloat16* __restrict__ Ahi, const __nv_bfloat16* __restrict__ Alo,
    const __nv_bfloat16* __restrict__ Wth, const __nv_bfloat16* __restrict__ Wtl,
    const float* __restrict__ bias,
    float* __restrict__ Cf, __nv_bfloat16* __restrict__ Chi, __nv_bfloat16* __restrict__ Clo,
    int M)
{
    extern __shared__ __align__(16) char smem[];
    __nv_bfloat16* sAh = (__nv_bfloat16*)(smem);
    __nv_bfloat16* sAl = (__nv_bfloat16*)(smem + 16384);
    __nv_bfloat16* sWh = (__nv_bfloat16*)(smem + 32768);
    __nv_bfloat16* sWl = (__nv_bfloat16*)(smem + 49152);
    uint32_t uAh = smem_u32(sAh), uAl = smem_u32(sAl);
    uint32_t uWh = smem_u32(sWh), uWl = smem_u32(sWl);

    int tid = threadIdx.x, lane = tid & 31, wid = tid >> 5;
    int wm = wid >> 1, wn = wid & 1;
    int bm = blockIdx.x * 128, bn = blockIdx.y * 128;

    float acc[2][8][4];
    #pragma unroll
    for (int s = 0; s < 2; s++)
        #pragma unroll
        for (int p = 0; p < 8; p++)
            #pragma unroll
            for (int q = 0; q < 4; q++) acc[s][p][q] = 0.f;

    // ldmatrix lane roles
    int a_r    = lane & 15;          // A: row within 16-row block
    int a_half = lane >> 4;          // A: k-chunk selector (0: kk, 1: kk+8)
    int b_nr   = ((lane >> 4) << 3) + (lane & 7);   // B: n row within 16
    int b_half = (lane >> 3) & 1;                   // B: k-chunk selector

    for (int k0 = 0; k0 < K; k0 += 64) {
        // ---- stage tiles into swizzled SMEM (1024 x 16B chunks per tile) ----
        for (int i = tid; i < 1024; i += 256) {
            int row = i >> 3, c = i & 7;
            int dst = (row * 8 + (c ^ (row & 7))) * 8;    // bf16 elems
            int grow = bm + row;
            float4 vh = make_float4(0.f, 0.f, 0.f, 0.f), vl = vh;
            if (grow < M) {
                vh = *(const float4*)(Ahi + (size_t)grow * K + k0 + c * 8);
                vl = *(const float4*)(Alo + (size_t)grow * K + k0 + c * 8);
            }
            *(float4*)(sAh + dst) = vh;
            *(float4*)(sAl + dst) = vl;
            int nrow = bn + row;   // N is multiple of 128, no guard
            *(float4*)(sWh + dst) = *(const float4*)(Wth + (size_t)nrow * K + k0 + c * 8);
            *(float4*)(sWl + dst) = *(const float4*)(Wtl + (size_t)nrow * K + k0 + c * 8);
        }
        __syncthreads();

        #pragma unroll
        for (int kk = 0; kk < 64; kk += 16) {
            uint32_t ah[2][4], al[2][4];
            #pragma unroll
            for (int s = 0; s < 2; s++) {
                int row = wm * 32 + s * 16 + a_r;
                int kc = (kk >> 3) + a_half;
                uint32_t off = (uint32_t)(row * 8 + (kc ^ (row & 7))) * 16;
                ldsm4(ah[s], uAh + off);
                ldsm4(al[s], uAl + off);
            }
            uint32_t bh[4][4], bl[4][4];
            #pragma unroll
            for (int p = 0; p < 4; p++) {
                int row = wn * 64 + p * 16 + b_nr;
                int kc = (kk >> 3) + b_half;
                uint32_t off = (uint32_t)(row * 8 + (kc ^ (row & 7))) * 16;
                ldsm4(bh[p], uWh + off);
                ldsm4(bl[p], uWl + off);
            }
            #pragma unroll
            for (int s = 0; s < 2; s++)
                #pragma unroll
                for (int p = 0; p < 4; p++)
                    #pragma unroll
                    for (int t = 0; t < 2; t++) {
                        float* c = acc[s][p * 2 + t];
                        mma16816(c, ah[s], bh[p][t * 2], bh[p][t * 2 + 1]);  // hiA*hiW
                        mma16816(c, ah[s], bl[p][t * 2], bl[p][t * 2 + 1]);  // hiA*loW
                        mma16816(c, al[s], bh[p][t * 2], bh[p][t * 2 + 1]);  // loA*hiW
                    }
        }
        __syncthreads();
    }

    // ---- epilogue ----
    int g = lane >> 2, t = lane & 3;
    #pragma unroll
    for (int s = 0; s < 2; s++) {
        int r0 = bm + wm * 32 + s * 16 + g;
        #pragma unroll
        for (int p8 = 0; p8 < 8; p8++) {
            int col = bn + wn * 64 + p8 * 8 + t * 2;
            float v0 = acc[s][p8][0], v1 = acc[s][p8][1];
            float v2 = acc[s][p8][2], v3 = acc[s][p8][3];
            if (BIAS) {
                float b0 = bias[col], b1 = bias[col + 1];
                v0 += b0; v1 += b1; v2 += b0; v3 += b1;
            }
            if (RELU) {
                v0 = fmaxf(v0, 0.f); v1 = fmaxf(v1, 0.f);
                v2 = fmaxf(v2, 0.f); v3 = fmaxf(v3, 0.f);
            }
            if (OUTBF16) {
                if (r0 < M) {
                    __nv_bfloat16 h0 = __float2bfloat16(v0), h1 = __float2bfloat16(v1);
                    __nv_bfloat162 hh; hh.x = h0; hh.y = h1;
                    __nv_bfloat162 ll;
                    ll.x = __float2bfloat16(v0 - __bfloat162float(h0));
                    ll.y = __float2bfloat16(v1 - __bfloat162float(h1));
                    *(__nv_bfloat162*)(Chi + (size_t)r0 * N + col) = hh;
                    *(__nv_bfloat162*)(Clo + (size_t)r0 * N + col) = ll;
                }
                if (r0 + 8 < M) {
                    __nv_bfloat16 h0 = __float2bfloat16(v2), h1 = __float2bfloat16(v3);
                    __nv_bfloat162 hh; hh.x = h0; hh.y = h1;
                    __nv_bfloat162 ll;
                    ll.x = __float2bfloat16(v2 - __bfloat162float(h0));
                    ll.y = __float2bfloat16(v3 - __bfloat162float(h1));
                    *(__nv_bfloat162*)(Chi + (size_t)(r0 + 8) * N + col) = hh;
                    *(__nv_bfloat162*)(Clo + (size_t)(r0 + 8) * N + col) = ll;
                }
            } else {
                if (r0 < M)     *(float2*)(Cf + (size_t)r0 * N + col)       = make_float2(v0, v1);
                if (r0 + 8 < M) *(float2*)(Cf + (size_t)(r0 + 8) * N + col) = make_float2(v2, v3);
            }
        }
    }
}

// ---------------- launch ----------------
extern "C" void kernel_launch(void* const* d_in, const int* in_sizes, int n_in,
                              void* d_out, int out_size)
{
    const float* x  = (const float*)d_in[0];
    const int*   ei = (const int*)  d_in[1];
    const float* W1 = (const float*)d_in[2];
    const float* b1 = (const float*)d_in[3];
    const float* W2 = (const float*)d_in[4];
    const float* b2 = (const float*)d_in[5];
    float* out = (float*)d_out;

    void *p_p, *p_ahi, *p_alo, *p_hhi, *p_hlo, *p_w1h, *p_w1l, *p_w2h, *p_w2l;
    cudaGetSymbolAddress(&p_p,   g_p);
    cudaGetSymbolAddress(&p_ahi, g_ahi);
    cudaGetSymbolAddress(&p_alo, g_alo);
    cudaGetSymbolAddress(&p_hhi, g_hhi);
    cudaGetSymbolAddress(&p_hlo, g_hlo);
    cudaGetSymbolAddress(&p_w1h, g_w1h);
    cudaGetSymbolAddress(&p_w1l, g_w1l);
    cudaGetSymbolAddress(&p_w2h, g_w2h);
    cudaGetSymbolAddress(&p_w2l, g_w2l);

    const int T = 256;
    const int SMEM_SZ = 65536;

    cudaFuncSetAttribute(k_mma<HID_CH, IN_CH, true, true, true>,
                         cudaFuncAttributeMaxDynamicSharedMemorySize, SMEM_SZ);
    cudaFuncSetAttribute(k_mma<OUT_CH, HID_CH, false, false, false>,
                         cudaFuncAttributeMaxDynamicSharedMemorySize, SMEM_SZ);

    // CSR build + weight prep
    k_zero_deg<<<(N_NODES + T - 1) / T, T>>>();
    k_count_deg<<<(N_EDGES + T - 1) / T, T>>>(ei);
    k_prep_w<<<(2 * 32768 + T - 1) / T, T>>>(W1, W2);
    k_scan<<<1, 1024>>>();
    k_fill_csr<<<(N_EDGES + T - 1) / T, T>>>(ei);

    int agrid = (N_NODES * 32 + T - 1) / T;   // one warp per node
    int mgrid = (N_NODES + 127) / 128;        // 391 M-blocks

    // ---- layer 1: gather-aggregate -> bf16 hi/lo, then tensor GEMM ----
    k_agg_bf16<<<agrid, T>>>(x, (__nv_bfloat16*)p_ahi, (__nv_bfloat16*)p_alo);
    {
        dim3 grid(mgrid, HID_CH / 128);
        k_mma<HID_CH, IN_CH, true, true, true><<<grid, 256, SMEM_SZ>>>(
            (const __nv_bfloat16*)p_ahi, (const __nv_bfloat16*)p_alo,
            (const __nv_bfloat16*)p_w1h, (const __nv_bfloat16*)p_w1l,
            b1, nullptr, (__nv_bfloat16*)p_hhi, (__nv_bfloat16*)p_hlo, N_NODES);
    }

    // ---- layer 2: tensor GEMM (fp32 out), then gather-aggregate + bias ----
    {
        dim3 grid(mgrid, OUT_CH / 128);
        k_mma<OUT_CH, HID_CH, false, false, false><<<grid, 256, SMEM_SZ>>>(
            (const __nv_bfloat16*)p_hhi, (const __nv_bfloat16*)p_hlo,
            (const __nv_bfloat16*)p_w2h, (const __nv_bfloat16*)p_w2l,
            nullptr, (float*)p_p, nullptr, nullptr, N_NODES);
    }
    k_agg<true><<<agrid, T>>>((const float*)p_p, out, b2);
}

// round 11
// speedup vs baseline: 2.1857x; 1.1959x over previous
#include <cuda_runtime.h>
#include <cuda_bf16.h>
#include <math.h>
#include <cstdint>

#define N_NODES 50000
#define N_EDGES 800000
#define IN_CH   128
#define HID_CH  256
#define OUT_CH  128

#define SCAN_BLK 1024
#define SCAN_NB  ((N_NODES + SCAN_BLK - 1) / SCAN_BLK)   // 49

// ---------------- scratch (__device__ globals; no allocation allowed) ----------------
__device__ int   g_deg[N_NODES];
__device__ float g_dinv[N_NODES];
__device__ int   g_rowstart[N_NODES + 1];
__device__ int   g_fill[N_NODES];
__device__ int   g_csr[N_EDGES];
__device__ int   g_bsum[SCAN_NB];
__device__ int   g_boff[SCAN_NB];
__device__ float g_p[(size_t)N_NODES * OUT_CH];              // h @ W2 (fp32)
// bf16 hi/lo split feature buffers
__device__ __nv_bfloat16 g_ahi[(size_t)N_NODES * IN_CH];     // layer-1 A (aggregated, dinv-scaled)
__device__ __nv_bfloat16 g_alo[(size_t)N_NODES * IN_CH];
__device__ __nv_bfloat16 g_hhi[(size_t)N_NODES * HID_CH];    // relu hidden
__device__ __nv_bfloat16 g_hlo[(size_t)N_NODES * HID_CH];
// transposed + split weights: Wt[n][k]
__device__ __nv_bfloat16 g_w1h[HID_CH * IN_CH];
__device__ __nv_bfloat16 g_w1l[HID_CH * IN_CH];
__device__ __nv_bfloat16 g_w2h[OUT_CH * HID_CH];
__device__ __nv_bfloat16 g_w2l[OUT_CH * HID_CH];

// ---------------- helpers ----------------
__device__ __forceinline__ uint32_t smem_u32(const void* p) {
    uint32_t a;
    asm("{ .reg .u64 t; cvta.to.shared.u64 t, %1; cvt.u32.u64 %0, t; }" : "=r"(a) : "l"(p));
    return a;
}
__device__ __forceinline__ void ldsm4(uint32_t* r, uint32_t addr) {
    asm volatile("ldmatrix.sync.aligned.m8n8.x4.shared.b16 {%0,%1,%2,%3}, [%4];"
        : "=r"(r[0]), "=r"(r[1]), "=r"(r[2]), "=r"(r[3]) : "r"(addr));
}
__device__ __forceinline__ void mma16816(float* c, const uint32_t* a, uint32_t b0, uint32_t b1) {
    asm volatile("mma.sync.aligned.m16n8k16.row.col.f32.bf16.bf16.f32 "
        "{%0,%1,%2,%3}, {%4,%5,%6,%7}, {%8,%9}, {%0,%1,%2,%3};"
        : "+f"(c[0]), "+f"(c[1]), "+f"(c[2]), "+f"(c[3])
        : "r"(a[0]), "r"(a[1]), "r"(a[2]), "r"(a[3]), "r"(b0), "r"(b1));
}

// ---------------- degree count (known good) ----------------
__global__ void k_zero_deg() {
    int i = blockIdx.x * blockDim.x + threadIdx.x;
    if (i < N_NODES) g_deg[i] = 0;
}

__global__ void k_count_deg(const int* __restrict__ ei) {
    int i = blockIdx.x * blockDim.x + threadIdx.x;
    if (i < N_EDGES) atomicAdd(&g_deg[ei[N_EDGES + i]], 1);
}

// ---------------- parallel scan: 3 passes ----------------
// pass A: per-block exclusive scan of deg (1024 elems/block) + block total + dinv
__global__ void __launch_bounds__(SCAN_BLK) k_scanA() {
    __shared__ int wsum[32];
    int tid = threadIdx.x, lane = tid & 31, wid = tid >> 5;
    int i = blockIdx.x * SCAN_BLK + tid;
    int d = (i < N_NODES) ? g_deg[i] : 0;
    int v = d;
    #pragma unroll
    for (int o = 1; o < 32; o <<= 1) {
        int t = __shfl_up_sync(0xffffffffu, v, o);
        if (lane >= o) v += t;
    }
    if (lane == 31) wsum[wid] = v;
    __syncthreads();
    if (wid == 0) {
        int w = wsum[lane];
        #pragma unroll
        for (int o = 1; o < 32; o <<= 1) {
            int t = __shfl_up_sync(0xffffffffu, w, o);
            if (lane >= o) w += t;
        }
        wsum[lane] = w;
    }
    __syncthreads();
    int excl = (wid ? wsum[wid - 1] : 0) + v - d;   // exclusive within block
    if (i < N_NODES) {
        g_rowstart[i] = excl;
        g_dinv[i] = rsqrtf((float)d + 1.0f);
    }
    if (tid == SCAN_BLK - 1) g_bsum[blockIdx.x] = excl + d;
}

// pass B: one block scans the SCAN_NB block totals (exclusive)
__global__ void k_scanB() {
    __shared__ int wsum[32];
    int tid = threadIdx.x, lane = tid & 31, wid = tid >> 5;
    int d = (tid < SCAN_NB) ? g_bsum[tid] : 0;
    int v = d;
    #pragma unroll
    for (int o = 1; o < 32; o <<= 1) {
        int t = __shfl_up_sync(0xffffffffu, v, o);
        if (lane >= o) v += t;
    }
    if (lane == 31) wsum[wid] = v;
    __syncthreads();
    if (wid == 0) {
        int w = wsum[lane];
        #pragma unroll
        for (int o = 1; o < 32; o <<= 1) {
            int t = __shfl_up_sync(0xffffffffu, w, o);
            if (lane >= o) w += t;
        }
        wsum[lane] = w;
    }
    __syncthreads();
    if (tid < SCAN_NB) g_boff[tid] = (wid ? wsum[wid - 1] : 0) + v - d;
}

// pass C: add block offsets, produce rowstart + fill
__global__ void k_scanC() {
    int i = blockIdx.x * blockDim.x + threadIdx.x;
    if (i < N_NODES) {
        int r = g_rowstart[i] + g_boff[i >> 10];
        g_rowstart[i] = r;
        g_fill[i] = r;
    }
    if (i == 0) g_rowstart[N_NODES] = N_EDGES;
}

__global__ void k_fill_csr(const int* __restrict__ ei) {
    int i = blockIdx.x * blockDim.x + threadIdx.x;
    if (i < N_EDGES) {
        int src = ei[i];
        int dst = ei[N_EDGES + i];
        int pos = atomicAdd(&g_fill[dst], 1);
        g_csr[pos] = src;
    }
}

// ---------------- gather aggregation, fp32 out (known good) ----------------
template<bool FINAL>
__global__ void __launch_bounds__(256) k_agg(
    const float* __restrict__ feat, float* __restrict__ outp,
    const float* __restrict__ bias)
{
    int n = (blockIdx.x * blockDim.x + threadIdx.x) >> 5;
    if (n >= N_NODES) return;
    int lane = threadIdx.x & 31;
    int start = g_rowstart[n];
    int end   = g_rowstart[n + 1];
    float dn = g_dinv[n];
    float4 self = *(const float4*)(feat + (size_t)n * 128 + lane * 4);
    float4 acc;
    acc.x = dn * self.x; acc.y = dn * self.y;
    acc.z = dn * self.z; acc.w = dn * self.w;

    for (int r = start; r < end; r += 32) {
        int ne = min(32, end - r);
        int s = 0; float w = 0.f;
        if (lane < ne) { s = g_csr[r + lane]; w = g_dinv[s]; }
        for (int j = 0; j < ne; j++) {
            int   sj = __shfl_sync(0xffffffffu, s, j);
            float wj = __shfl_sync(0xffffffffu, w, j);
            float4 v = *(const float4*)(feat + (size_t)sj * 128 + lane * 4);
            acc.x = fmaf(wj, v.x, acc.x);
            acc.y = fmaf(wj, v.y, acc.y);
            acc.z = fmaf(wj, v.z, acc.z);
            acc.w = fmaf(wj, v.w, acc.w);
        }
    }
    if (FINAL) {
        float4 b = *(const float4*)(bias + lane * 4);
        acc.x = fmaf(dn, acc.x, b.x);
        acc.y = fmaf(dn, acc.y, b.y);
        acc.z = fmaf(dn, acc.z, b.z);
        acc.w = fmaf(dn, acc.w, b.w);
    }
    *(float4*)(outp + (size_t)n * 128 + lane * 4) = acc;
}

// ---------------- layer-1 aggregation, bf16 hi/lo out with fused outer dinv ----------------
__global__ void __launch_bounds__(256) k_agg_bf16(
    const float* __restrict__ feat,
    __nv_bfloat16* __restrict__ ohi, __nv_bfloat16* __restrict__ olo)
{
    int n = (blockIdx.x * blockDim.x + threadIdx.x) >> 5;
    if (n >= N_NODES) return;
    int lane = threadIdx.x & 31;
    int start = g_rowstart[n];
    int end   = g_rowstart[n + 1];
    float dn = g_dinv[n];
    float4 self = *(const float4*)(feat + (size_t)n * 128 + lane * 4);
    float4 acc;
    acc.x = dn * self.x; acc.y = dn * self.y;
    acc.z = dn * self.z; acc.w = dn * self.w;

    for (int r = start; r < end; r += 32) {
        int ne = min(32, end - r);
        int s = 0; float w = 0.f;
        if (lane < ne) { s = g_csr[r + lane]; w = g_dinv[s]; }
        for (int j = 0; j < ne; j++) {
            int   sj = __shfl_sync(0xffffffffu, s, j);
            float wj = __shfl_sync(0xffffffffu, w, j);
            float4 v = *(const float4*)(feat + (size_t)sj * 128 + lane * 4);
            acc.x = fmaf(wj, v.x, acc.x);
            acc.y = fmaf(wj, v.y, acc.y);
            acc.z = fmaf(wj, v.z, acc.z);
            acc.w = fmaf(wj, v.w, acc.w);
        }
    }
    acc.x *= dn; acc.y *= dn; acc.z *= dn; acc.w *= dn;

    float f[4] = {acc.x, acc.y, acc.z, acc.w};
    __nv_bfloat16 hi[4], lo[4];
    #pragma unroll
    for (int j = 0; j < 4; j++) {
        hi[j] = __float2bfloat16(f[j]);
        lo[j] = __float2bfloat16(f[j] - __bfloat162float(hi[j]));
    }
    size_t o = (size_t)n * 128 + lane * 4;
    __nv_bfloat162 h0; h0.x = hi[0]; h0.y = hi[1];
    __nv_bfloat162 h1; h1.x = hi[2]; h1.y = hi[3];
    __nv_bfloat162 l0; l0.x = lo[0]; l0.y = lo[1];
    __nv_bfloat162 l1; l1.x = lo[2]; l1.y = lo[3];
    *(__nv_bfloat162*)(ohi + o)     = h0;
    *(__nv_bfloat162*)(ohi + o + 2) = h1;
    *(__nv_bfloat162*)(olo + o)     = l0;
    *(__nv_bfloat162*)(olo + o + 2) = l1;
}

// ---------------- weight prep: fp32 W[K][N] -> transposed Wt[n][k] bf16 hi/lo ----------------
__global__ void k_prep_w(const float* __restrict__ W1, const float* __restrict__ W2) {
    int idx = blockIdx.x * blockDim.x + threadIdx.x;
    if (idx >= 2 * 32768) return;
    int which = idx >> 15;
    int e = idx & 32767;
    if (which == 0) {
        int n = e & 255, k = e >> 8;            // n < 256, k < 128
        float w = W1[k * 256 + n];
        __nv_bfloat16 hi = __float2bfloat16(w);
        __nv_bfloat16 lo = __float2bfloat16(w - __bfloat162float(hi));
        g_w1h[n * 128 + k] = hi;
        g_w1l[n * 128 + k] = lo;
    } else {
        int n = e & 127, k = e >> 7;            // n < 128, k < 256
        float w = W2[k * 128 + n];
        __nv_bfloat16 hi = __float2bfloat16(w);
        __nv_bfloat16 lo = __float2bfloat16(w - __bfloat162float(hi));
        g_w2h[n * 256 + k] = hi;
        g_w2l[n * 256 + k] = lo;
    }
}

// ---------------- bf16 mma.sync GEMM (R10 verbatim, known good) ----------------
template<int N, int K, bool OUTBF16, bool RELU, bool BIAS>
__global__ void __launch_bounds__(256) k_mma(
    const __nv_bfloat16* __restrict__ Ahi, const __nv_bfloat16* __restrict__ Alo,
    const __nv_bfloat16* __restrict__ Wth, const __nv_bfloat16* __restrict__ Wtl,
    const float* __restrict__ bias,
    float* __restrict__ Cf, __nv_bfloat16* __restrict__ Chi, __nv_bfloat16* __restrict__ Clo,
    int M)
{
    extern __shared__ __align__(16) char smem[];
    __nv_bfloat16* sAh = (__nv_bfloat16*)(smem);
    __nv_bfloat16* sAl = (__nv_bfloat16*)(smem + 16384);
    __nv_bfloat16* sWh = (__nv_bfloat16*)(smem + 32768);
    __nv_bfloat16* sWl = (__nv_bfloat16*)(smem + 49152);
    uint32_t uAh = smem_u32(sAh), uAl = smem_u32(sAl);
    uint32_t uWh = smem_u32(sWh), uWl = smem_u32(sWl);

    int tid = threadIdx.x, lane = tid & 31, wid = tid >> 5;
    int wm = wid >> 1, wn = wid & 1;
    int bm = blockIdx.x * 128, bn = blockIdx.y * 128;

    float acc[2][8][4];
    #pragma unroll
    for (int s = 0; s < 2; s++)
        #pragma unroll
        for (int p = 0; p < 8; p++)
            #pragma unroll
            for (int q = 0; q < 4; q++) acc[s][p][q] = 0.f;

    int a_r    = lane & 15;
    int a_half = lane >> 4;
    int b_nr   = ((lane >> 4) << 3) + (lane & 7);
    int b_half = (lane >> 3) & 1;

    for (int k0 = 0; k0 < K; k0 += 64) {
        for (int i = tid; i < 1024; i += 256) {
            int row = i >> 3, c = i & 7;
            int dst = (row * 8 + (c ^ (row & 7))) * 8;
            int grow = bm + row;
            float4 vh = make_float4(0.f, 0.f, 0.f, 0.f), vl = vh;
            if (grow < M) {
                vh = *(const float4*)(Ahi + (size_t)grow * K + k0 + c * 8);
                vl = *(const float4*)(Alo + (size_t)grow * K + k0 + c * 8);
            }
            *(float4*)(sAh + dst) = vh;
            *(float4*)(sAl + dst) = vl;
            int nrow = bn + row;
            *(float4*)(sWh + dst) = *(const float4*)(Wth + (size_t)nrow * K + k0 + c * 8);
            *(float4*)(sWl + dst) = *(const float4*)(Wtl + (size_t)nrow * K + k0 + c * 8);
        }
        __syncthreads();

        #pragma unroll
        for (int kk = 0; kk < 64; kk += 16) {
            uint32_t ah[2][4], al[2][4];
            #pragma unroll
            for (int s = 0; s < 2; s++) {
                int row = wm * 32 + s * 16 + a_r;
                int kc = (kk >> 3) + a_half;
                uint32_t off = (uint32_t)(row * 8 + (kc ^ (row & 7))) * 16;
                ldsm4(ah[s], uAh + off);
                ldsm4(al[s], uAl + off);
            }
            uint32_t bh[4][4], bl[4][4];
            #pragma unroll
            for (int p = 0; p < 4; p++) {
                int row = wn * 64 + p * 16 + b_nr;
                int kc = (kk >> 3) + b_half;
                uint32_t off = (uint32_t)(row * 8 + (kc ^ (row & 7))) * 16;
                ldsm4(bh[p], uWh + off);
                ldsm4(bl[p], uWl + off);
            }
            #pragma unroll
            for (int s = 0; s < 2; s++)
                #pragma unroll
                for (int p = 0; p < 4; p++)
                    #pragma unroll
                    for (int t = 0; t < 2; t++) {
                        float* c = acc[s][p * 2 + t];
                        mma16816(c, ah[s], bh[p][t * 2], bh[p][t * 2 + 1]);
                        mma16816(c, ah[s], bl[p][t * 2], bl[p][t * 2 + 1]);
                        mma16816(c, al[s], bh[p][t * 2], bh[p][t * 2 + 1]);
                    }
        }
        __syncthreads();
    }

    int g = lane >> 2, t = lane & 3;
    #pragma unroll
    for (int s = 0; s < 2; s++) {
        int r0 = bm + wm * 32 + s * 16 + g;
        #pragma unroll
        for (int p8 = 0; p8 < 8; p8++) {
            int col = bn + wn * 64 + p8 * 8 + t * 2;
            float v0 = acc[s][p8][0], v1 = acc[s][p8][1];
            float v2 = acc[s][p8][2], v3 = acc[s][p8][3];
            if (BIAS) {
                float b0 = bias[col], b1 = bias[col + 1];
                v0 += b0; v1 += b1; v2 += b0; v3 += b1;
            }
            if (RELU) {
                v0 = fmaxf(v0, 0.f); v1 = fmaxf(v1, 0.f);
                v2 = fmaxf(v2, 0.f); v3 = fmaxf(v3, 0.f);
            }
            if (OUTBF16) {
                if (r0 < M) {
                    __nv_bfloat16 h0 = __float2bfloat16(v0), h1 = __float2bfloat16(v1);
                    __nv_bfloat162 hh; hh.x = h0; hh.y = h1;
                    __nv_bfloat162 ll;
                    ll.x = __float2bfloat16(v0 - __bfloat162float(h0));
                    ll.y = __float2bfloat16(v1 - __bfloat162float(h1));
                    *(__nv_bfloat162*)(Chi + (size_t)r0 * N + col) = hh;
                    *(__nv_bfloat162*)(Clo + (size_t)r0 * N + col) = ll;
                }
                if (r0 + 8 < M) {
                    __nv_bfloat16 h0 = __float2bfloat16(v2), h1 = __float2bfloat16(v3);
                    __nv_bfloat162 hh; hh.x = h0; hh.y = h1;
                    __nv_bfloat162 ll;
                    ll.x = __float2bfloat16(v2 - __bfloat162float(h0));
                    ll.y = __float2bfloat16(v3 - __bfloat162float(h1));
                    *(__nv_bfloat162*)(Chi + (size_t)(r0 + 8) * N + col) = hh;
                    *(__nv_bfloat162*)(Clo + (size_t)(r0 + 8) * N + col) = ll;
                }
            } else {
                if (r0 < M)     *(float2*)(Cf + (size_t)r0 * N + col)       = make_float2(v0, v1);
                if (r0 + 8 < M) *(float2*)(Cf + (size_t)(r0 + 8) * N + col) = make_float2(v2, v3);
            }
        }
    }
}

// ---------------- launch ----------------
extern "C" void kernel_launch(void* const* d_in, const int* in_sizes, int n_in,
                              void* d_out, int out_size)
{
    const float* x  = (const float*)d_in[0];
    const int*   ei = (const int*)  d_in[1];
    const float* W1 = (const float*)d_in[2];
    const float* b1 = (const float*)d_in[3];
    const float* W2 = (const float*)d_in[4];
    const float* b2 = (const float*)d_in[5];
    float* out = (float*)d_out;

    void *p_p, *p_ahi, *p_alo, *p_hhi, *p_hlo, *p_w1h, *p_w1l, *p_w2h, *p_w2l;
    cudaGetSymbolAddress(&p_p,   g_p);
    cudaGetSymbolAddress(&p_ahi, g_ahi);
    cudaGetSymbolAddress(&p_alo, g_alo);
    cudaGetSymbolAddress(&p_hhi, g_hhi);
    cudaGetSymbolAddress(&p_hlo, g_hlo);
    cudaGetSymbolAddress(&p_w1h, g_w1h);
    cudaGetSymbolAddress(&p_w1l, g_w1l);
    cudaGetSymbolAddress(&p_w2h, g_w2h);
    cudaGetSymbolAddress(&p_w2l, g_w2l);

    const int T = 256;
    const int SMEM_SZ = 65536;

    cudaFuncSetAttribute(k_mma<HID_CH, IN_CH, true, true, true>,
                         cudaFuncAttributeMaxDynamicSharedMemorySize, SMEM_SZ);
    cudaFuncSetAttribute(k_mma<OUT_CH, HID_CH, false, false, false>,
                         cudaFuncAttributeMaxDynamicSharedMemorySize, SMEM_SZ);

    // CSR build + weight prep
    k_zero_deg<<<(N_NODES + T - 1) / T, T>>>();
    k_count_deg<<<(N_EDGES + T - 1) / T, T>>>(ei);
    k_prep_w<<<(2 * 32768 + T - 1) / T, T>>>(W1, W2);
    k_scanA<<<SCAN_NB, SCAN_BLK>>>();
    k_scanB<<<1, 64>>>();
    k_scanC<<<(N_NODES + T - 1) / T, T>>>();
    k_fill_csr<<<(N_EDGES + T - 1) / T, T>>>(ei);

    int agrid = (N_NODES * 32 + T - 1) / T;   // one warp per node
    int mgrid = (N_NODES + 127) / 128;        // 391 M-blocks

    // ---- layer 1: gather-aggregate -> bf16 hi/lo, then tensor GEMM ----
    k_agg_bf16<<<agrid, T>>>(x, (__nv_bfloat16*)p_ahi, (__nv_bfloat16*)p_alo);
    {
        dim3 grid(mgrid, HID_CH / 128);
        k_mma<HID_CH, IN_CH, true, true, true><<<grid, 256, SMEM_SZ>>>(
            (const __nv_bfloat16*)p_ahi, (const __nv_bfloat16*)p_alo,
            (const __nv_bfloat16*)p_w1h, (const __nv_bfloat16*)p_w1l,
            b1, nullptr, (__nv_bfloat16*)p_hhi, (__nv_bfloat16*)p_hlo, N_NODES);
    }

    // ---- layer 2: tensor GEMM (fp32 out), then gather-aggregate + bias ----
    {
        dim3 grid(mgrid, OUT_CH / 128);
        k_mma<OUT_CH, HID_CH, false, false, false><<<grid, 256, SMEM_SZ>>>(
            (const __nv_bfloat16*)p_hhi, (const __nv_bfloat16*)p_hlo,
            (const __nv_bfloat16*)p_w2h, (const __nv_bfloat16*)p_w2l,
            nullptr, (float*)p_p, nullptr, nullptr, N_NODES);
    }
    k_agg<true><<<agrid, T>>>((const float*)p_p, out, b2);
}

// round 12
// speedup vs baseline: 2.3486x; 1.0745x over previous
#include <cuda_runtime.h>
#include <cuda_bf16.h>
#include <math.h>
#include <cstdint>

#define N_NODES 50000
#define N_EDGES 800000
#define IN_CH   128
#define HID_CH  256
#define OUT_CH  128

#define SCAN_BLK 1024
#define SCAN_NB  ((N_NODES + SCAN_BLK - 1) / SCAN_BLK)   // 49

// ---------------- scratch (__device__ globals; no allocation allowed) ----------------
__device__ int   g_deg[N_NODES];
__device__ float g_dinv[N_NODES];
__device__ int   g_rowstart[N_NODES + 1];
__device__ int   g_fill[N_NODES];
__device__ int   g_csr[N_EDGES];
__device__ int   g_bsum[SCAN_NB];
__device__ int   g_boff[SCAN_NB];
__device__ float g_p[(size_t)N_NODES * OUT_CH];              // h @ W2 (fp32)
__device__ __nv_bfloat16 g_ahi[(size_t)N_NODES * IN_CH];
__device__ __nv_bfloat16 g_alo[(size_t)N_NODES * IN_CH];
__device__ __nv_bfloat16 g_hhi[(size_t)N_NODES * HID_CH];
__device__ __nv_bfloat16 g_hlo[(size_t)N_NODES * HID_CH];
__device__ __nv_bfloat16 g_w1h[HID_CH * IN_CH];
__device__ __nv_bfloat16 g_w1l[HID_CH * IN_CH];
__device__ __nv_bfloat16 g_w2h[OUT_CH * HID_CH];
__device__ __nv_bfloat16 g_w2l[OUT_CH * HID_CH];

// ---------------- helpers ----------------
__device__ __forceinline__ uint32_t smem_u32(const void* p) {
    uint32_t a;
    asm("{ .reg .u64 t; cvta.to.shared.u64 t, %1; cvt.u32.u64 %0, t; }" : "=r"(a) : "l"(p));
    return a;
}
__device__ __forceinline__ void ldsm4(uint32_t* r, uint32_t addr) {
    asm volatile("ldmatrix.sync.aligned.m8n8.x4.shared.b16 {%0,%1,%2,%3}, [%4];"
        : "=r"(r[0]), "=r"(r[1]), "=r"(r[2]), "=r"(r[3]) : "r"(addr));
}
__device__ __forceinline__ void mma16816(float* c, const uint32_t* a, uint32_t b0, uint32_t b1) {
    asm volatile("mma.sync.aligned.m16n8k16.row.col.f32.bf16.bf16.f32 "
        "{%0,%1,%2,%3}, {%4,%5,%6,%7}, {%8,%9}, {%0,%1,%2,%3};"
        : "+f"(c[0]), "+f"(c[1]), "+f"(c[2]), "+f"(c[3])
        : "r"(a[0]), "r"(a[1]), "r"(a[2]), "r"(a[3]), "r"(b0), "r"(b1));
}
__device__ __forceinline__ void cpa16(uint32_t saddr, const void* gaddr, uint32_t srcsz) {
    asm volatile("cp.async.ca.shared.global [%0], [%1], 16, %2;"
                 :: "r"(saddr), "l"(gaddr), "r"(srcsz) : "memory");
}
__device__ __forceinline__ void cpa_commit() {
    asm volatile("cp.async.commit_group;" ::: "memory");
}
template<int N_>
__device__ __forceinline__ void cpa_wait() {
    asm volatile("cp.async.wait_group %0;" :: "n"(N_) : "memory");
}

// ---------------- degree count (known good) ----------------
__global__ void k_zero_deg() {
    int i = blockIdx.x * blockDim.x + threadIdx.x;
    if (i < N_NODES) g_deg[i] = 0;
}

__global__ void k_count_deg(const int* __restrict__ ei) {
    int i = blockIdx.x * blockDim.x + threadIdx.x;
    if (i < N_EDGES) atomicAdd(&g_deg[ei[N_EDGES + i]], 1);
}

// ---------------- parallel scan: 3 passes (R11 verbatim, known good) ----------------
__global__ void __launch_bounds__(SCAN_BLK) k_scanA() {
    __shared__ int wsum[32];
    int tid = threadIdx.x, lane = tid & 31, wid = tid >> 5;
    int i = blockIdx.x * SCAN_BLK + tid;
    int d = (i < N_NODES) ? g_deg[i] : 0;
    int v = d;
    #pragma unroll
    for (int o = 1; o < 32; o <<= 1) {
        int t = __shfl_up_sync(0xffffffffu, v, o);
        if (lane >= o) v += t;
    }
    if (lane == 31) wsum[wid] = v;
    __syncthreads();
    if (wid == 0) {
        int w = wsum[lane];
        #pragma unroll
        for (int o = 1; o < 32; o <<= 1) {
            int t = __shfl_up_sync(0xffffffffu, w, o);
            if (lane >= o) w += t;
        }
        wsum[lane] = w;
    }
    __syncthreads();
    int excl = (wid ? wsum[wid - 1] : 0) + v - d;
    if (i < N_NODES) {
        g_rowstart[i] = excl;
        g_dinv[i] = rsqrtf((float)d + 1.0f);
    }
    if (tid == SCAN_BLK - 1) g_bsum[blockIdx.x] = excl + d;
}

__global__ void k_scanB() {
    __shared__ int wsum[32];
    int tid = threadIdx.x, lane = tid & 31, wid = tid >> 5;
    int d = (tid < SCAN_NB) ? g_bsum[tid] : 0;
    int v = d;
    #pragma unroll
    for (int o = 1; o < 32; o <<= 1) {
        int t = __shfl_up_sync(0xffffffffu, v, o);
        if (lane >= o) v += t;
    }
    if (lane == 31) wsum[wid] = v;
    __syncthreads();
    if (wid == 0) {
        int w = wsum[lane];
        #pragma unroll
        for (int o = 1; o < 32; o <<= 1) {
            int t = __shfl_up_sync(0xffffffffu, w, o);
            if (lane >= o) w += t;
        }
        wsum[lane] = w;
    }
    __syncthreads();
    if (tid < SCAN_NB) g_boff[tid] = (wid ? wsum[wid - 1] : 0) + v - d;
}

__global__ void k_scanC() {
    int i = blockIdx.x * blockDim.x + threadIdx.x;
    if (i < N_NODES) {
        int r = g_rowstart[i] + g_boff[i >> 10];
        g_rowstart[i] = r;
        g_fill[i] = r;
    }
    if (i == 0) g_rowstart[N_NODES] = N_EDGES;
}

__global__ void k_fill_csr(const int* __restrict__ ei) {
    int i = blockIdx.x * blockDim.x + threadIdx.x;
    if (i < N_EDGES) {
        int src = ei[i];
        int dst = ei[N_EDGES + i];
        int pos = atomicAdd(&g_fill[dst], 1);
        g_csr[pos] = src;
    }
}

// ---------------- gather aggregation, fp32 out (known good) ----------------
template<bool FINAL>
__global__ void __launch_bounds__(256) k_agg(
    const float* __restrict__ feat, float* __restrict__ outp,
    const float* __restrict__ bias)
{
    int n = (blockIdx.x * blockDim.x + threadIdx.x) >> 5;
    if (n >= N_NODES) return;
    int lane = threadIdx.x & 31;
    int start = g_rowstart[n];
    int end   = g_rowstart[n + 1];
    float dn = g_dinv[n];
    float4 self = *(const float4*)(feat + (size_t)n * 128 + lane * 4);
    float4 acc;
    acc.x = dn * self.x; acc.y = dn * self.y;
    acc.z = dn * self.z; acc.w = dn * self.w;

    for (int r = start; r < end; r += 32) {
        int ne = min(32, end - r);
        int s = 0; float w = 0.f;
        if (lane < ne) { s = g_csr[r + lane]; w = g_dinv[s]; }
        for (int j = 0; j < ne; j++) {
            int   sj = __shfl_sync(0xffffffffu, s, j);
            float wj = __shfl_sync(0xffffffffu, w, j);
            float4 v = *(const float4*)(feat + (size_t)sj * 128 + lane * 4);
            acc.x = fmaf(wj, v.x, acc.x);
            acc.y = fmaf(wj, v.y, acc.y);
            acc.z = fmaf(wj, v.z, acc.z);
            acc.w = fmaf(wj, v.w, acc.w);
        }
    }
    if (FINAL) {
        float4 b = *(const float4*)(bias + lane * 4);
        acc.x = fmaf(dn, acc.x, b.x);
        acc.y = fmaf(dn, acc.y, b.y);
        acc.z = fmaf(dn, acc.z, b.z);
        acc.w = fmaf(dn, acc.w, b.w);
    }
    *(float4*)(outp + (size_t)n * 128 + lane * 4) = acc;
}

// ---------------- layer-1 aggregation, bf16 hi/lo out (known good) ----------------
__global__ void __launch_bounds__(256) k_agg_bf16(
    const float* __restrict__ feat,
    __nv_bfloat16* __restrict__ ohi, __nv_bfloat16* __restrict__ olo)
{
    int n = (blockIdx.x * blockDim.x + threadIdx.x) >> 5;
    if (n >= N_NODES) return;
    int lane = threadIdx.x & 31;
    int start = g_rowstart[n];
    int end   = g_rowstart[n + 1];
    float dn = g_dinv[n];
    float4 self = *(const float4*)(feat + (size_t)n * 128 + lane * 4);
    float4 acc;
    acc.x = dn * self.x; acc.y = dn * self.y;
    acc.z = dn * self.z; acc.w = dn * self.w;

    for (int r = start; r < end; r += 32) {
        int ne = min(32, end - r);
        int s = 0; float w = 0.f;
        if (lane < ne) { s = g_csr[r + lane]; w = g_dinv[s]; }
        for (int j = 0; j < ne; j++) {
            int   sj = __shfl_sync(0xffffffffu, s, j);
            float wj = __shfl_sync(0xffffffffu, w, j);
            float4 v = *(const float4*)(feat + (size_t)sj * 128 + lane * 4);
            acc.x = fmaf(wj, v.x, acc.x);
            acc.y = fmaf(wj, v.y, acc.y);
            acc.z = fmaf(wj, v.z, acc.z);
            acc.w = fmaf(wj, v.w, acc.w);
        }
    }
    acc.x *= dn; acc.y *= dn; acc.z *= dn; acc.w *= dn;

    float f[4] = {acc.x, acc.y, acc.z, acc.w};
    __nv_bfloat16 hi[4], lo[4];
    #pragma unroll
    for (int j = 0; j < 4; j++) {
        hi[j] = __float2bfloat16(f[j]);
        lo[j] = __float2bfloat16(f[j] - __bfloat162float(hi[j]));
    }
    size_t o = (size_t)n * 128 + lane * 4;
    __nv_bfloat162 h0; h0.x = hi[0]; h0.y = hi[1];
    __nv_bfloat162 h1; h1.x = hi[2]; h1.y = hi[3];
    __nv_bfloat162 l0; l0.x = lo[0]; l0.y = lo[1];
    __nv_bfloat162 l1; l1.x = lo[2]; l1.y = lo[3];
    *(__nv_bfloat162*)(ohi + o)     = h0;
    *(__nv_bfloat162*)(ohi + o + 2) = h1;
    *(__nv_bfloat162*)(olo + o)     = l0;
    *(__nv_bfloat162*)(olo + o + 2) = l1;
}

// ---------------- weight prep (known good) ----------------
__global__ void k_prep_w(const float* __restrict__ W1, const float* __restrict__ W2) {
    int idx = blockIdx.x * blockDim.x + threadIdx.x;
    if (idx >= 2 * 32768) return;
    int which = idx >> 15;
    int e = idx & 32767;
    if (which == 0) {
        int n = e & 255, k = e >> 8;
        float w = W1[k * 256 + n];
        __nv_bfloat16 hi = __float2bfloat16(w);
        __nv_bfloat16 lo = __float2bfloat16(w - __bfloat162float(hi));
        g_w1h[n * 128 + k] = hi;
        g_w1l[n * 128 + k] = lo;
    } else {
        int n = e & 127, k = e >> 7;
        float w = W2[k * 128 + n];
        __nv_bfloat16 hi = __float2bfloat16(w);
        __nv_bfloat16 lo = __float2bfloat16(w - __bfloat162float(hi));
        g_w2h[n * 256 + k] = hi;
        g_w2l[n * 256 + k] = lo;
    }
}

// ---------------- bf16 mma.sync GEMM with cp.async 2-stage pipeline ----------------
// CTA 256 thr (8 warps, 4Mx2N), tile 128x128, BK=32, warp tile m32 x n64.
// SMEM: per stage 4 arrays [128 rows x 32 bf16], row stride 80B (padded, ldmatrix
// bank pattern r*20 mod 32 distinct within 8 rows). 2 stages = 81920B.
template<int N, int K, bool OUTBF16, bool RELU, bool BIAS>
__global__ void __launch_bounds__(256) k_mma(
    const __nv_bfloat16* __restrict__ Ahi, const __nv_bfloat16* __restrict__ Alo,
    const __nv_bfloat16* __restrict__ Wth, const __nv_bfloat16* __restrict__ Wtl,
    const float* __restrict__ bias,
    float* __restrict__ Cf, __nv_bfloat16* __restrict__ Chi, __nv_bfloat16* __restrict__ Clo,
    int M)
{
    constexpr int STG = 40960;           // bytes per stage
    constexpr int O_AH = 0, O_AL = 10240, O_WH = 20480, O_WL = 30720;
    constexpr int NK = K / 32;

    extern __shared__ __align__(16) char smem[];
    uint32_t su = smem_u32(smem);

    int tid = threadIdx.x, lane = tid & 31, wid = tid >> 5;
    int wm = wid >> 1, wn = wid & 1;
    int bm = blockIdx.x * 128, bn = blockIdx.y * 128;

    float acc[2][8][4];
    #pragma unroll
    for (int s = 0; s < 2; s++)
        #pragma unroll
        for (int p = 0; p < 8; p++)
            #pragma unroll
            for (int q = 0; q < 4; q++) acc[s][p][q] = 0.f;

    int a_r    = lane & 15;
    int a_half = lane >> 4;
    int b_nr   = ((lane >> 4) << 3) + (lane & 7);
    int b_half = (lane >> 3) & 1;

    // stage loader: 512 chunks per array / 256 thr = 2 per array per thread
    auto load_stage = [&](int st, int k0) {
        uint32_t base = su + st * STG;
        #pragma unroll
        for (int ii = 0; ii < 2; ii++) {
            int i = tid + ii * 256;
            int row = i >> 2, c = i & 3;
            uint32_t soff = (uint32_t)row * 80 + c * 16;
            // A (M-guarded, zfill)
            int grow = bm + row;
            uint32_t pA = (grow < M) ? 16u : 0u;
            int crow = grow < M ? grow : (M - 1);
            cpa16(base + O_AH + soff, Ahi + (size_t)crow * K + k0 + c * 8, pA);
            cpa16(base + O_AL + soff, Alo + (size_t)crow * K + k0 + c * 8, pA);
            // W (N multiple of 128, no guard)
            int nrow = bn + row;
            cpa16(base + O_WH + soff, Wth + (size_t)nrow * K + k0 + c * 8, 16u);
            cpa16(base + O_WL + soff, Wtl + (size_t)nrow * K + k0 + c * 8, 16u);
        }
        cpa_commit();
    };

    load_stage(0, 0);

    for (int k0i = 0; k0i < NK; k0i++) {
        int buf = k0i & 1;
        if (k0i + 1 < NK) {
            load_stage(buf ^ 1, (k0i + 1) * 32);
            cpa_wait<1>();
        } else {
            cpa_wait<0>();
        }
        __syncthreads();

        uint32_t bA = su + buf * STG;
        #pragma unroll
        for (int kk = 0; kk < 32; kk += 16) {
            uint32_t ah[2][4], al[2][4];
            #pragma unroll
            for (int s = 0; s < 2; s++) {
                int row = wm * 32 + s * 16 + a_r;
                int kc = (kk >> 3) + a_half;
                uint32_t off = (uint32_t)row * 80 + kc * 16;
                ldsm4(ah[s], bA + O_AH + off);
                ldsm4(al[s], bA + O_AL + off);
            }
            uint32_t bh[4][4], bl[4][4];
            #pragma unroll
            for (int p = 0; p < 4; p++) {
                int row = wn * 64 + p * 16 + b_nr;
                int kc = (kk >> 3) + b_half;
                uint32_t off = (uint32_t)row * 80 + kc * 16;
                ldsm4(bh[p], bA + O_WH + off);
                ldsm4(bl[p], bA + O_WL + off);
            }
            #pragma unroll
            for (int s = 0; s < 2; s++)
                #pragma unroll
                for (int p = 0; p < 4; p++)
                    #pragma unroll
                    for (int t = 0; t < 2; t++) {
                        float* c = acc[s][p * 2 + t];
                        mma16816(c, ah[s], bh[p][t * 2], bh[p][t * 2 + 1]);
                        mma16816(c, ah[s], bl[p][t * 2], bl[p][t * 2 + 1]);
                        mma16816(c, al[s], bh[p][t * 2], bh[p][t * 2 + 1]);
                    }
        }
        __syncthreads();
    }

    // ---- epilogue (R11 verbatim) ----
    int g = lane >> 2, t = lane & 3;
    #pragma unroll
    for (int s = 0; s < 2; s++) {
        int r0 = bm + wm * 32 + s * 16 + g;
        #pragma unroll
        for (int p8 = 0; p8 < 8; p8++) {
            int col = bn + wn * 64 + p8 * 8 + t * 2;
            float v0 = acc[s][p8][0], v1 = acc[s][p8][1];
            float v2 = acc[s][p8][2], v3 = acc[s][p8][3];
            if (BIAS) {
                float b0 = bias[col], b1 = bias[col + 1];
                v0 += b0; v1 += b1; v2 += b0; v3 += b1;
            }
            if (RELU) {
                v0 = fmaxf(v0, 0.f); v1 = fmaxf(v1, 0.f);
                v2 = fmaxf(v2, 0.f); v3 = fmaxf(v3, 0.f);
            }
            if (OUTBF16) {
                if (r0 < M) {
                    __nv_bfloat16 h0 = __float2bfloat16(v0), h1 = __float2bfloat16(v1);
                    __nv_bfloat162 hh; hh.x = h0; hh.y = h1;
                    __nv_bfloat162 ll;
                    ll.x = __float2bfloat16(v0 - __bfloat162float(h0));
                    ll.y = __float2bfloat16(v1 - __bfloat162float(h1));
                    *(__nv_bfloat162*)(Chi + (size_t)r0 * N + col) = hh;
                    *(__nv_bfloat162*)(Clo + (size_t)r0 * N + col) = ll;
                }
                if (r0 + 8 < M) {
                    __nv_bfloat16 h0 = __float2bfloat16(v2), h1 = __float2bfloat16(v3);
                    __nv_bfloat162 hh; hh.x = h0; hh.y = h1;
                    __nv_bfloat162 ll;
                    ll.x = __float2bfloat16(v2 - __bfloat162float(h0));
                    ll.y = __float2bfloat16(v3 - __bfloat162float(h1));
                    *(__nv_bfloat162*)(Chi + (size_t)(r0 + 8) * N + col) = hh;
                    *(__nv_bfloat162*)(Clo + (size_t)(r0 + 8) * N + col) = ll;
                }
            } else {
                if (r0 < M)     *(float2*)(Cf + (size_t)r0 * N + col)       = make_float2(v0, v1);
                if (r0 + 8 < M) *(float2*)(Cf + (size_t)(r0 + 8) * N + col) = make_float2(v2, v3);
            }
        }
    }
}

// ---------------- launch ----------------
extern "C" void kernel_launch(void* const* d_in, const int* in_sizes, int n_in,
                              void* d_out, int out_size)
{
    const float* x  = (const float*)d_in[0];
    const int*   ei = (const int*)  d_in[1];
    const float* W1 = (const float*)d_in[2];
    const float* b1 = (const float*)d_in[3];
    const float* W2 = (const float*)d_in[4];
    const float* b2 = (const float*)d_in[5];
    float* out = (float*)d_out;

    void *p_p, *p_ahi, *p_alo, *p_hhi, *p_hlo, *p_w1h, *p_w1l, *p_w2h, *p_w2l;
    cudaGetSymbolAddress(&p_p,   g_p);
    cudaGetSymbolAddress(&p_ahi, g_ahi);
    cudaGetSymbolAddress(&p_alo, g_alo);
    cudaGetSymbolAddress(&p_hhi, g_hhi);
    cudaGetSymbolAddress(&p_hlo, g_hlo);
    cudaGetSymbolAddress(&p_w1h, g_w1h);
    cudaGetSymbolAddress(&p_w1l, g_w1l);
    cudaGetSymbolAddress(&p_w2h, g_w2h);
    cudaGetSymbolAddress(&p_w2l, g_w2l);

    const int T = 256;
    const int SMEM_SZ = 81920;

    cudaFuncSetAttribute(k_mma<HID_CH, IN_CH, true, true, true>,
                         cudaFuncAttributeMaxDynamicSharedMemorySize, SMEM_SZ);
    cudaFuncSetAttribute(k_mma<OUT_CH, HID_CH, false, false, false>,
                         cudaFuncAttributeMaxDynamicSharedMemorySize, SMEM_SZ);

    // CSR build + weight prep
    k_zero_deg<<<(N_NODES + T - 1) / T, T>>>();
    k_count_deg<<<(N_EDGES + T - 1) / T, T>>>(ei);
    k_prep_w<<<(2 * 32768 + T - 1) / T, T>>>(W1, W2);
    k_scanA<<<SCAN_NB, SCAN_BLK>>>();
    k_scanB<<<1, 64>>>();
    k_scanC<<<(N_NODES + T - 1) / T, T>>>();
    k_fill_csr<<<(N_EDGES + T - 1) / T, T>>>(ei);

    int agrid = (N_NODES * 32 + T - 1) / T;   // one warp per node
    int mgrid = (N_NODES + 127) / 128;        // 391 M-blocks

    // ---- layer 1: gather-aggregate -> bf16 hi/lo, then tensor GEMM ----
    k_agg_bf16<<<agrid, T>>>(x, (__nv_bfloat16*)p_ahi, (__nv_bfloat16*)p_alo);
    {
        dim3 grid(mgrid, HID_CH / 128);
        k_mma<HID_CH, IN_CH, true, true, true><<<grid, 256, SMEM_SZ>>>(
            (const __nv_bfloat16*)p_ahi, (const __nv_bfloat16*)p_alo,
            (const __nv_bfloat16*)p_w1h, (const __nv_bfloat16*)p_w1l,
            b1, nullptr, (__nv_bfloat16*)p_hhi, (__nv_bfloat16*)p_hlo, N_NODES);
    }

    // ---- layer 2: tensor GEMM (fp32 out), then gather-aggregate + bias ----
    {
        dim3 grid(mgrid, OUT_CH / 128);
        k_mma<OUT_CH, HID_CH, false, false, false><<<grid, 256, SMEM_SZ>>>(
            (const __nv_bfloat16*)p_hhi, (const __nv_bfloat16*)p_hlo,
            (const __nv_bfloat16*)p_w2h, (const __nv_bfloat16*)p_w2l,
            nullptr, (float*)p_p, nullptr, nullptr, N_NODES);
    }
    k_agg<true><<<agrid, T>>>((const float*)p_p, out, b2);
}

// round 13
// speedup vs baseline: 2.3868x; 1.0163x over previous
#include <cuda_runtime.h>
#include <cuda_bf16.h>
#include <cuda_fp16.h>
#include <math.h>
#include <cstdint>

#define N_NODES 50000
#define N_EDGES 800000
#define IN_CH   128
#define HID_CH  256
#define OUT_CH  128

#define SCAN_BLK 1024
#define SCAN_NB  ((N_NODES + SCAN_BLK - 1) / SCAN_BLK)   // 49

// ---------------- scratch (__device__ globals; no allocation allowed) ----------------
__device__ int   g_deg[N_NODES];
__device__ float g_dinv[N_NODES];
__device__ int   g_rowstart[N_NODES + 1];
__device__ int   g_fill[N_NODES];
__device__ int   g_csr[N_EDGES];
__device__ int   g_bsum[SCAN_NB];
__device__ int   g_boff[SCAN_NB];
__device__ __half g_pf16[(size_t)N_NODES * OUT_CH];          // h @ W2 (fp16)
__device__ __nv_bfloat16 g_ahi[(size_t)N_NODES * IN_CH];
__device__ __nv_bfloat16 g_alo[(size_t)N_NODES * IN_CH];
__device__ __nv_bfloat16 g_hhi[(size_t)N_NODES * HID_CH];
__device__ __nv_bfloat16 g_hlo[(size_t)N_NODES * HID_CH];
__device__ __nv_bfloat16 g_w1h[HID_CH * IN_CH];
__device__ __nv_bfloat16 g_w1l[HID_CH * IN_CH];
__device__ __nv_bfloat16 g_w2h[OUT_CH * HID_CH];
__device__ __nv_bfloat16 g_w2l[OUT_CH * HID_CH];

// ---------------- helpers ----------------
__device__ __forceinline__ uint32_t smem_u32(const void* p) {
    uint32_t a;
    asm("{ .reg .u64 t; cvta.to.shared.u64 t, %1; cvt.u32.u64 %0, t; }" : "=r"(a) : "l"(p));
    return a;
}
__device__ __forceinline__ void ldsm4(uint32_t* r, uint32_t addr) {
    asm volatile("ldmatrix.sync.aligned.m8n8.x4.shared.b16 {%0,%1,%2,%3}, [%4];"
        : "=r"(r[0]), "=r"(r[1]), "=r"(r[2]), "=r"(r[3]) : "r"(addr));
}
__device__ __forceinline__ void mma16816(float* c, const uint32_t* a, uint32_t b0, uint32_t b1) {
    asm volatile("mma.sync.aligned.m16n8k16.row.col.f32.bf16.bf16.f32 "
        "{%0,%1,%2,%3}, {%4,%5,%6,%7}, {%8,%9}, {%0,%1,%2,%3};"
        : "+f"(c[0]), "+f"(c[1]), "+f"(c[2]), "+f"(c[3])
        : "r"(a[0]), "r"(a[1]), "r"(a[2]), "r"(a[3]), "r"(b0), "r"(b1));
}
__device__ __forceinline__ void cpa16(uint32_t saddr, const void* gaddr, uint32_t srcsz) {
    asm volatile("cp.async.ca.shared.global [%0], [%1], 16, %2;"
                 :: "r"(saddr), "l"(gaddr), "r"(srcsz) : "memory");
}
__device__ __forceinline__ void cpa_commit() {
    asm volatile("cp.async.commit_group;" ::: "memory");
}
template<int N_>
__device__ __forceinline__ void cpa_wait() {
    asm volatile("cp.async.wait_group %0;" :: "n"(N_) : "memory");
}

// ---------------- degree count ----------------
__global__ void k_count_deg(const int* __restrict__ ei) {
    int i = blockIdx.x * blockDim.x + threadIdx.x;
    if (i < N_EDGES) atomicAdd(&g_deg[ei[N_EDGES + i]], 1);
}

// ---------------- parallel scan: 3 passes (known good) ----------------
__global__ void __launch_bounds__(SCAN_BLK) k_scanA() {
    __shared__ int wsum[32];
    int tid = threadIdx.x, lane = tid & 31, wid = tid >> 5;
    int i = blockIdx.x * SCAN_BLK + tid;
    int d = (i < N_NODES) ? g_deg[i] : 0;
    int v = d;
    #pragma unroll
    for (int o = 1; o < 32; o <<= 1) {
        int t = __shfl_up_sync(0xffffffffu, v, o);
        if (lane >= o) v += t;
    }
    if (lane == 31) wsum[wid] = v;
    __syncthreads();
    if (wid == 0) {
        int w = wsum[lane];
        #pragma unroll
        for (int o = 1; o < 32; o <<= 1) {
            int t = __shfl_up_sync(0xffffffffu, w, o);
            if (lane >= o) w += t;
        }
        wsum[lane] = w;
    }
    __syncthreads();
    int excl = (wid ? wsum[wid - 1] : 0) + v - d;
    if (i < N_NODES) {
        g_rowstart[i] = excl;
        g_dinv[i] = rsqrtf((float)d + 1.0f);
    }
    if (tid == SCAN_BLK - 1) g_bsum[blockIdx.x] = excl + d;
}

__global__ void k_scanB() {
    __shared__ int wsum[32];
    int tid = threadIdx.x, lane = tid & 31, wid = tid >> 5;
    int d = (tid < SCAN_NB) ? g_bsum[tid] : 0;
    int v = d;
    #pragma unroll
    for (int o = 1; o < 32; o <<= 1) {
        int t = __shfl_up_sync(0xffffffffu, v, o);
        if (lane >= o) v += t;
    }
    if (lane == 31) wsum[wid] = v;
    __syncthreads();
    if (wid == 0) {
        int w = wsum[lane];
        #pragma unroll
        for (int o = 1; o < 32; o <<= 1) {
            int t = __shfl_up_sync(0xffffffffu, w, o);
            if (lane >= o) w += t;
        }
        wsum[lane] = w;
    }
    __syncthreads();
    if (tid < SCAN_NB) g_boff[tid] = (wid ? wsum[wid - 1] : 0) + v - d;
}

__global__ void k_scanC() {
    int i = blockIdx.x * blockDim.x + threadIdx.x;
    if (i < N_NODES) {
        int r = g_rowstart[i] + g_boff[i >> 10];
        g_rowstart[i] = r;
        g_fill[i] = r;
    }
    if (i == 0) g_rowstart[N_NODES] = N_EDGES;
}

__global__ void k_fill_csr(const int* __restrict__ ei) {
    int i = blockIdx.x * blockDim.x + threadIdx.x;
    if (i < N_EDGES) {
        int src = ei[i];
        int dst = ei[N_EDGES + i];
        int pos = atomicAdd(&g_fill[dst], 1);
        g_csr[pos] = src;
    }
}

// ---------------- final aggregation from fp16 rows, fp32 out ----------------
// out[n] = dinv[n]*( dinv[n]*p[n] + sum dinv[s]*p[s] ) + b2
__global__ void __launch_bounds__(256) k_agg_f16(
    const __half* __restrict__ feat, float* __restrict__ outp,
    const float* __restrict__ bias)
{
    int n = (blockIdx.x * blockDim.x + threadIdx.x) >> 5;
    if (n >= N_NODES) return;
    int lane = threadIdx.x & 31;
    int start = g_rowstart[n];
    int end   = g_rowstart[n + 1];
    float dn = g_dinv[n];

    uint2 raw = *(const uint2*)(feat + (size_t)n * 128 + lane * 4);
    float2 s01 = __half22float2(*(__half2*)&raw.x);
    float2 s23 = __half22float2(*(__half2*)&raw.y);
    float4 acc;
    acc.x = dn * s01.x; acc.y = dn * s01.y;
    acc.z = dn * s23.x; acc.w = dn * s23.y;

    for (int r = start; r < end; r += 32) {
        int ne = min(32, end - r);
        int s = 0; float w = 0.f;
        if (lane < ne) { s = g_csr[r + lane]; w = g_dinv[s]; }
        for (int j = 0; j < ne; j++) {
            int   sj = __shfl_sync(0xffffffffu, s, j);
            float wj = __shfl_sync(0xffffffffu, w, j);
            uint2 rv = *(const uint2*)(feat + (size_t)sj * 128 + lane * 4);
            float2 v01 = __half22float2(*(__half2*)&rv.x);
            float2 v23 = __half22float2(*(__half2*)&rv.y);
            acc.x = fmaf(wj, v01.x, acc.x);
            acc.y = fmaf(wj, v01.y, acc.y);
            acc.z = fmaf(wj, v23.x, acc.z);
            acc.w = fmaf(wj, v23.y, acc.w);
        }
    }
    float4 b = *(const float4*)(bias + lane * 4);
    acc.x = fmaf(dn, acc.x, b.x);
    acc.y = fmaf(dn, acc.y, b.y);
    acc.z = fmaf(dn, acc.z, b.z);
    acc.w = fmaf(dn, acc.w, b.w);
    *(float4*)(outp + (size_t)n * 128 + lane * 4) = acc;
}

// ---------------- layer-1 aggregation, bf16 hi/lo out (known good) ----------------
__global__ void __launch_bounds__(256) k_agg_bf16(
    const float* __restrict__ feat,
    __nv_bfloat16* __restrict__ ohi, __nv_bfloat16* __restrict__ olo)
{
    int n = (blockIdx.x * blockDim.x + threadIdx.x) >> 5;
    if (n >= N_NODES) return;
    int lane = threadIdx.x & 31;
    int start = g_rowstart[n];
    int end   = g_rowstart[n + 1];
    float dn = g_dinv[n];
    float4 self = *(const float4*)(feat + (size_t)n * 128 + lane * 4);
    float4 acc;
    acc.x = dn * self.x; acc.y = dn * self.y;
    acc.z = dn * self.z; acc.w = dn * self.w;

    for (int r = start; r < end; r += 32) {
        int ne = min(32, end - r);
        int s = 0; float w = 0.f;
        if (lane < ne) { s = g_csr[r + lane]; w = g_dinv[s]; }
        for (int j = 0; j < ne; j++) {
            int   sj = __shfl_sync(0xffffffffu, s, j);
            float wj = __shfl_sync(0xffffffffu, w, j);
            float4 v = *(const float4*)(feat + (size_t)sj * 128 + lane * 4);
            acc.x = fmaf(wj, v.x, acc.x);
            acc.y = fmaf(wj, v.y, acc.y);
            acc.z = fmaf(wj, v.z, acc.z);
            acc.w = fmaf(wj, v.w, acc.w);
        }
    }
    acc.x *= dn; acc.y *= dn; acc.z *= dn; acc.w *= dn;

    float f[4] = {acc.x, acc.y, acc.z, acc.w};
    __nv_bfloat16 hi[4], lo[4];
    #pragma unroll
    for (int j = 0; j < 4; j++) {
        hi[j] = __float2bfloat16(f[j]);
        lo[j] = __float2bfloat16(f[j] - __bfloat162float(hi[j]));
    }
    size_t o = (size_t)n * 128 + lane * 4;
    __nv_bfloat162 h0; h0.x = hi[0]; h0.y = hi[1];
    __nv_bfloat162 h1; h1.x = hi[2]; h1.y = hi[3];
    __nv_bfloat162 l0; l0.x = lo[0]; l0.y = lo[1];
    __nv_bfloat162 l1; l1.x = lo[2]; l1.y = lo[3];
    *(__nv_bfloat162*)(ohi + o)     = h0;
    *(__nv_bfloat162*)(ohi + o + 2) = h1;
    *(__nv_bfloat162*)(olo + o)     = l0;
    *(__nv_bfloat162*)(olo + o + 2) = l1;
}

// ---------------- weight prep (known good) ----------------
__global__ void k_prep_w(const float* __restrict__ W1, const float* __restrict__ W2) {
    int idx = blockIdx.x * blockDim.x + threadIdx.x;
    if (idx >= 2 * 32768) return;
    int which = idx >> 15;
    int e = idx & 32767;
    if (which == 0) {
        int n = e & 255, k = e >> 8;
        float w = W1[k * 256 + n];
        __nv_bfloat16 hi = __float2bfloat16(w);
        __nv_bfloat16 lo = __float2bfloat16(w - __bfloat162float(hi));
        g_w1h[n * 128 + k] = hi;
        g_w1l[n * 128 + k] = lo;
    } else {
        int n = e & 127, k = e >> 7;
        float w = W2[k * 128 + n];
        __nv_bfloat16 hi = __float2bfloat16(w);
        __nv_bfloat16 lo = __float2bfloat16(w - __bfloat162float(hi));
        g_w2h[n * 256 + k] = hi;
        g_w2l[n * 256 + k] = lo;
    }
}

// ---------------- bf16 mma.sync GEMM with cp.async 2-stage pipeline ----------------
// OUTMODE: 0 = fp32, 1 = bf16 hi/lo, 2 = fp16
template<int N, int K, int OUTMODE, bool RELU, bool BIAS>
__global__ void __launch_bounds__(256) k_mma(
    const __nv_bfloat16* __restrict__ Ahi, const __nv_bfloat16* __restrict__ Alo,
    const __nv_bfloat16* __restrict__ Wth, const __nv_bfloat16* __restrict__ Wtl,
    const float* __restrict__ bias,
    __half* __restrict__ Ch, __nv_bfloat16* __restrict__ Chi, __nv_bfloat16* __restrict__ Clo,
    int M)
{
    constexpr int STG = 40960;
    constexpr int O_AH = 0, O_AL = 10240, O_WH = 20480, O_WL = 30720;
    constexpr int NK = K / 32;

    extern __shared__ __align__(16) char smem[];
    uint32_t su = smem_u32(smem);

    int tid = threadIdx.x, lane = tid & 31, wid = tid >> 5;
    int wm = wid >> 1, wn = wid & 1;
    int bm = blockIdx.x * 128, bn = blockIdx.y * 128;

    float acc[2][8][4];
    #pragma unroll
    for (int s = 0; s < 2; s++)
        #pragma unroll
        for (int p = 0; p < 8; p++)
            #pragma unroll
            for (int q = 0; q < 4; q++) acc[s][p][q] = 0.f;

    int a_r    = lane & 15;
    int a_half = lane >> 4;
    int b_nr   = ((lane >> 4) << 3) + (lane & 7);
    int b_half = (lane >> 3) & 1;

    auto load_stage = [&](int st, int k0) {
        uint32_t base = su + st * STG;
        #pragma unroll
        for (int ii = 0; ii < 2; ii++) {
            int i = tid + ii * 256;
            int row = i >> 2, c = i & 3;
            uint32_t soff = (uint32_t)row * 80 + c * 16;
            int grow = bm + row;
            uint32_t pA = (grow < M) ? 16u : 0u;
            int crow = grow < M ? grow : (M - 1);
            cpa16(base + O_AH + soff, Ahi + (size_t)crow * K + k0 + c * 8, pA);
            cpa16(base + O_AL + soff, Alo + (size_t)crow * K + k0 + c * 8, pA);
            int nrow = bn + row;
            cpa16(base + O_WH + soff, Wth + (size_t)nrow * K + k0 + c * 8, 16u);
            cpa16(base + O_WL + soff, Wtl + (size_t)nrow * K + k0 + c * 8, 16u);
        }
        cpa_commit();
    };

    load_stage(0, 0);

    for (int k0i = 0; k0i < NK; k0i++) {
        int buf = k0i & 1;
        if (k0i + 1 < NK) {
            load_stage(buf ^ 1, (k0i + 1) * 32);
            cpa_wait<1>();
        } else {
            cpa_wait<0>();
        }
        __syncthreads();

        uint32_t bA = su + buf * STG;
        #pragma unroll
        for (int kk = 0; kk < 32; kk += 16) {
            uint32_t ah[2][4], al[2][4];
            #pragma unroll
            for (int s = 0; s < 2; s++) {
                int row = wm * 32 + s * 16 + a_r;
                int kc = (kk >> 3) + a_half;
                uint32_t off = (uint32_t)row * 80 + kc * 16;
                ldsm4(ah[s], bA + O_AH + off);
                ldsm4(al[s], bA + O_AL + off);
            }
            uint32_t bh[4][4], bl[4][4];
            #pragma unroll
            for (int p = 0; p < 4; p++) {
                int row = wn * 64 + p * 16 + b_nr;
                int kc = (kk >> 3) + b_half;
                uint32_t off = (uint32_t)row * 80 + kc * 16;
                ldsm4(bh[p], bA + O_WH + off);
                ldsm4(bl[p], bA + O_WL + off);
            }
            #pragma unroll
            for (int s = 0; s < 2; s++)
                #pragma unroll
                for (int p = 0; p < 4; p++)
                    #pragma unroll
                    for (int t = 0; t < 2; t++) {
                        float* c = acc[s][p * 2 + t];
                        mma16816(c, ah[s], bh[p][t * 2], bh[p][t * 2 + 1]);
                        mma16816(c, ah[s], bl[p][t * 2], bl[p][t * 2 + 1]);
                        mma16816(c, al[s], bh[p][t * 2], bh[p][t * 2 + 1]);
                    }
        }
        __syncthreads();
    }

    // ---- epilogue ----
    int g = lane >> 2, t = lane & 3;
    #pragma unroll
    for (int s = 0; s < 2; s++) {
        int r0 = bm + wm * 32 + s * 16 + g;
        #pragma unroll
        for (int p8 = 0; p8 < 8; p8++) {
            int col = bn + wn * 64 + p8 * 8 + t * 2;
            float v0 = acc[s][p8][0], v1 = acc[s][p8][1];
            float v2 = acc[s][p8][2], v3 = acc[s][p8][3];
            if (BIAS) {
                float b0 = bias[col], b1 = bias[col + 1];
                v0 += b0; v1 += b1; v2 += b0; v3 += b1;
            }
            if (RELU) {
                v0 = fmaxf(v0, 0.f); v1 = fmaxf(v1, 0.f);
                v2 = fmaxf(v2, 0.f); v3 = fmaxf(v3, 0.f);
            }
            if (OUTMODE == 1) {
                if (r0 < M) {
                    __nv_bfloat16 h0 = __float2bfloat16(v0), h1 = __float2bfloat16(v1);
                    __nv_bfloat162 hh; hh.x = h0; hh.y = h1;
                    __nv_bfloat162 ll;
                    ll.x = __float2bfloat16(v0 - __bfloat162float(h0));
                    ll.y = __float2bfloat16(v1 - __bfloat162float(h1));
                    *(__nv_bfloat162*)(Chi + (size_t)r0 * N + col) = hh;
                    *(__nv_bfloat162*)(Clo + (size_t)r0 * N + col) = ll;
                }
                if (r0 + 8 < M) {
                    __nv_bfloat16 h0 = __float2bfloat16(v2), h1 = __float2bfloat16(v3);
                    __nv_bfloat162 hh; hh.x = h0; hh.y = h1;
                    __nv_bfloat162 ll;
                    ll.x = __float2bfloat16(v2 - __bfloat162float(h0));
                    ll.y = __float2bfloat16(v3 - __bfloat162float(h1));
                    *(__nv_bfloat162*)(Chi + (size_t)(r0 + 8) * N + col) = hh;
                    *(__nv_bfloat162*)(Clo + (size_t)(r0 + 8) * N + col) = ll;
                }
            } else if (OUTMODE == 2) {
                if (r0 < M)
                    *(__half2*)(Ch + (size_t)r0 * N + col) = __floats2half2_rn(v0, v1);
                if (r0 + 8 < M)
                    *(__half2*)(Ch + (size_t)(r0 + 8) * N + col) = __floats2half2_rn(v2, v3);
            }
        }
    }
}

// ---------------- launch ----------------
extern "C" void kernel_launch(void* const* d_in, const int* in_sizes, int n_in,
                              void* d_out, int out_size)
{
    const float* x  = (const float*)d_in[0];
    const int*   ei = (const int*)  d_in[1];
    const float* W1 = (const float*)d_in[2];
    const float* b1 = (const float*)d_in[3];
    const float* W2 = (const float*)d_in[4];
    const float* b2 = (const float*)d_in[5];
    float* out = (float*)d_out;

    void *p_deg, *p_pf, *p_ahi, *p_alo, *p_hhi, *p_hlo, *p_w1h, *p_w1l, *p_w2h, *p_w2l;
    cudaGetSymbolAddress(&p_deg, g_deg);
    cudaGetSymbolAddress(&p_pf,  g_pf16);
    cudaGetSymbolAddress(&p_ahi, g_ahi);
    cudaGetSymbolAddress(&p_alo, g_alo);
    cudaGetSymbolAddress(&p_hhi, g_hhi);
    cudaGetSymbolAddress(&p_hlo, g_hlo);
    cudaGetSymbolAddress(&p_w1h, g_w1h);
    cudaGetSymbolAddress(&p_w1l, g_w1l);
    cudaGetSymbolAddress(&p_w2h, g_w2h);
    cudaGetSymbolAddress(&p_w2l, g_w2l);

    const int T = 256;
    const int SMEM_SZ = 81920;

    cudaFuncSetAttribute(k_mma<HID_CH, IN_CH, 1, true, true>,
                         cudaFuncAttributeMaxDynamicSharedMemorySize, SMEM_SZ);
    cudaFuncSetAttribute(k_mma<OUT_CH, HID_CH, 2, false, false>,
                         cudaFuncAttributeMaxDynamicSharedMemorySize, SMEM_SZ);

    // CSR build + weight prep
    cudaMemsetAsync(p_deg, 0, N_NODES * sizeof(int));
    k_count_deg<<<(N_EDGES + T - 1) / T, T>>>(ei);
    k_prep_w<<<(2 * 32768 + T - 1) / T, T>>>(W1, W2);
    k_scanA<<<SCAN_NB, SCAN_BLK>>>();
    k_scanB<<<1, 64>>>();
    k_scanC<<<(N_NODES + T - 1) / T, T>>>();
    k_fill_csr<<<(N_EDGES + T - 1) / T, T>>>(ei);

    int agrid = (N_NODES * 32 + T - 1) / T;   // one warp per node
    int mgrid = (N_NODES + 127) / 128;        // 391 M-blocks

    // ---- layer 1: gather-aggregate -> bf16 hi/lo, then tensor GEMM ----
    k_agg_bf16<<<agrid, T>>>(x, (__nv_bfloat16*)p_ahi, (__nv_bfloat16*)p_alo);
    {
        dim3 grid(mgrid, HID_CH / 128);
        k_mma<HID_CH, IN_CH, 1, true, true><<<grid, 256, SMEM_SZ>>>(
            (const __nv_bfloat16*)p_ahi, (const __nv_bfloat16*)p_alo,
            (const __nv_bfloat16*)p_w1h, (const __nv_bfloat16*)p_w1l,
            b1, nullptr, (__nv_bfloat16*)p_hhi, (__nv_bfloat16*)p_hlo, N_NODES);
    }

    // ---- layer 2: tensor GEMM (fp16 out), then gather-aggregate + bias ----
    {
        dim3 grid(mgrid, OUT_CH / 128);
        k_mma<OUT_CH, HID_CH, 2, false, false><<<grid, 256, SMEM_SZ>>>(
            (const __nv_bfloat16*)p_hhi, (const __nv_bfloat16*)p_hlo,
            (const __nv_bfloat16*)p_w2h, (const __nv_bfloat16*)p_w2l,
            nullptr, (__half*)p_pf, nullptr, nullptr, N_NODES);
    }
    k_agg_f16<<<agrid, T>>>((const __half*)p_pf, out, b2);
}

// round 14
// speedup vs baseline: 2.4218x; 1.0147x over previous
#include <cuda_runtime.h>
#include <cuda_bf16.h>
#include <cuda_fp16.h>
#include <math.h>
#include <cstdint>

#define N_NODES 50000
#define N_EDGES 800000
#define IN_CH   128
#define HID_CH  256
#define OUT_CH  128

#define SCAN_BLK 1024
#define SCAN_NB  ((N_NODES + SCAN_BLK - 1) / SCAN_BLK)   // 49
#define CD_BLOCKS ((N_EDGES + 255) / 256)                // 3125
#define PW_BLOCKS ((2 * 32768 + 255) / 256)              // 256

// ---------------- scratch (__device__ globals; no allocation allowed) ----------------
__device__ int   g_deg[N_NODES];
__device__ float g_dinv[N_NODES];
__device__ int   g_rowstart[N_NODES + 1];
__device__ int   g_fill[N_NODES];
__device__ int   g_csr[N_EDGES];
__device__ int   g_bsum[SCAN_NB];
__device__ int   g_bflag[SCAN_NB];
__device__ __half g_pf16[(size_t)N_NODES * OUT_CH];          // h @ W2 (fp16)
__device__ __nv_bfloat16 g_ahi[(size_t)N_NODES * IN_CH];
__device__ __nv_bfloat16 g_alo[(size_t)N_NODES * IN_CH];
__device__ __nv_bfloat16 g_hhi[(size_t)N_NODES * HID_CH];
__device__ __nv_bfloat16 g_hlo[(size_t)N_NODES * HID_CH];
__device__ __nv_bfloat16 g_w1h[HID_CH * IN_CH];
__device__ __nv_bfloat16 g_w1l[HID_CH * IN_CH];
__device__ __nv_bfloat16 g_w2h[OUT_CH * HID_CH];
__device__ __nv_bfloat16 g_w2l[OUT_CH * HID_CH];

// ---------------- helpers ----------------
__device__ __forceinline__ uint32_t smem_u32(const void* p) {
    uint32_t a;
    asm("{ .reg .u64 t; cvta.to.shared.u64 t, %1; cvt.u32.u64 %0, t; }" : "=r"(a) : "l"(p));
    return a;
}
__device__ __forceinline__ void ldsm4(uint32_t* r, uint32_t addr) {
    asm volatile("ldmatrix.sync.aligned.m8n8.x4.shared.b16 {%0,%1,%2,%3}, [%4];"
        : "=r"(r[0]), "=r"(r[1]), "=r"(r[2]), "=r"(r[3]) : "r"(addr));
}
__device__ __forceinline__ void mma16816(float* c, const uint32_t* a, uint32_t b0, uint32_t b1) {
    asm volatile("mma.sync.aligned.m16n8k16.row.col.f32.bf16.bf16.f32 "
        "{%0,%1,%2,%3}, {%4,%5,%6,%7}, {%8,%9}, {%0,%1,%2,%3};"
        : "+f"(c[0]), "+f"(c[1]), "+f"(c[2]), "+f"(c[3])
        : "r"(a[0]), "r"(a[1]), "r"(a[2]), "r"(a[3]), "r"(b0), "r"(b1));
}
__device__ __forceinline__ void cpa16(uint32_t saddr, const void* gaddr, uint32_t srcsz) {
    asm volatile("cp.async.ca.shared.global [%0], [%1], 16, %2;"
                 :: "r"(saddr), "l"(gaddr), "r"(srcsz) : "memory");
}
__device__ __forceinline__ void cpa_commit() {
    asm volatile("cp.async.commit_group;" ::: "memory");
}
template<int N_>
__device__ __forceinline__ void cpa_wait() {
    asm volatile("cp.async.wait_group %0;" :: "n"(N_) : "memory");
}

// ---------------- fused: degree count + weight prep + scan-flag zero ----------------
__global__ void k_count_prep(const int* __restrict__ ei,
                             const float* __restrict__ W1, const float* __restrict__ W2) {
    int b = blockIdx.x, tid = threadIdx.x;
    if (b == 0 && tid < SCAN_NB) g_bflag[tid] = 0;
    if (b < CD_BLOCKS) {
        int i = b * 256 + tid;
        if (i < N_EDGES) atomicAdd(&g_deg[ei[N_EDGES + i]], 1);
    } else {
        int idx = (b - CD_BLOCKS) * 256 + tid;
        if (idx >= 2 * 32768) return;
        int which = idx >> 15;
        int e = idx & 32767;
        if (which == 0) {
            int n = e & 255, k = e >> 8;
            float w = W1[k * 256 + n];
            __nv_bfloat16 hi = __float2bfloat16(w);
            __nv_bfloat16 lo = __float2bfloat16(w - __bfloat162float(hi));
            g_w1h[n * 128 + k] = hi;
            g_w1l[n * 128 + k] = lo;
        } else {
            int n = e & 127, k = e >> 7;
            float w = W2[k * 128 + n];
            __nv_bfloat16 hi = __float2bfloat16(w);
            __nv_bfloat16 lo = __float2bfloat16(w - __bfloat162float(hi));
            g_w2h[n * 256 + k] = hi;
            g_w2l[n * 256 + k] = lo;
        }
    }
}

// ---------------- single-kernel scan with decoupled lookback ----------------
// 49 blocks x 1024 thr (all resident on 148 SMs -> spin-wait safe, deterministic)
__global__ void __launch_bounds__(SCAN_BLK) k_scan_fused() {
    __shared__ int wsum[32];
    __shared__ int s_pref;
    __shared__ int s_par[2];
    int tid = threadIdx.x, lane = tid & 31, wid = tid >> 5;
    int bid = blockIdx.x;
    int i = bid * SCAN_BLK + tid;
    int d = (i < N_NODES) ? g_deg[i] : 0;
    int v = d;
    #pragma unroll
    for (int o = 1; o < 32; o <<= 1) {
        int t = __shfl_up_sync(0xffffffffu, v, o);
        if (lane >= o) v += t;
    }
    if (lane == 31) wsum[wid] = v;
    __syncthreads();
    if (wid == 0) {
        int w = wsum[lane];
        #pragma unroll
        for (int o = 1; o < 32; o <<= 1) {
            int t = __shfl_up_sync(0xffffffffu, w, o);
            if (lane >= o) w += t;
        }
        wsum[lane] = w;
    }
    __syncthreads();
    int excl = (wid ? wsum[wid - 1] : 0) + v - d;

    // publish block total, then lookback-sum all predecessors in parallel
    if (tid == 0) {
        g_bsum[bid] = wsum[31];
        __threadfence();
        atomicExch(&g_bflag[bid], 1);
    }
    int pv = 0;
    if (tid < 64) {
        if (tid < bid) {
            while (atomicAdd(&g_bflag[tid], 0) == 0) {}
            pv = g_bsum[tid];
        }
        #pragma unroll
        for (int o = 16; o; o >>= 1) pv += __shfl_down_sync(0xffffffffu, pv, o);
        if ((tid & 31) == 0) s_par[tid >> 5] = pv;
    }
    __syncthreads();
    if (tid == 0) s_pref = s_par[0] + s_par[1];
    __syncthreads();
    int pref = s_pref;

    if (i < N_NODES) {
        int r = excl + pref;
        g_rowstart[i] = r;
        g_fill[i] = r;
        g_dinv[i] = rsqrtf((float)d + 1.0f);
    }
    if (i == 0) g_rowstart[N_NODES] = N_EDGES;
}

__global__ void k_fill_csr(const int* __restrict__ ei) {
    int i = blockIdx.x * blockDim.x + threadIdx.x;
    if (i < N_EDGES) {
        int src = ei[i];
        int dst = ei[N_EDGES + i];
        int pos = atomicAdd(&g_fill[dst], 1);
        g_csr[pos] = src;
    }
}

// ---------------- layer-1 aggregation, bf16 hi/lo out, MLP-4 unrolled ----------------
__global__ void __launch_bounds__(256) k_agg_bf16(
    const float* __restrict__ feat,
    __nv_bfloat16* __restrict__ ohi, __nv_bfloat16* __restrict__ olo)
{
    int n = (blockIdx.x * blockDim.x + threadIdx.x) >> 5;
    if (n >= N_NODES) return;
    int lane = threadIdx.x & 31;
    int start = g_rowstart[n];
    int end   = g_rowstart[n + 1];
    float dn = g_dinv[n];
    float4 self = *(const float4*)(feat + (size_t)n * 128 + lane * 4);
    float4 acc;
    acc.x = dn * self.x; acc.y = dn * self.y;
    acc.z = dn * self.z; acc.w = dn * self.w;

    for (int r = start; r < end; r += 32) {
        int ne = min(32, end - r);
        int s = 0; float w = 0.f;
        if (lane < ne) { s = g_csr[r + lane]; w = g_dinv[s]; }
        int j = 0;
        for (; j + 4 <= ne; j += 4) {
            int s0 = __shfl_sync(0xffffffffu, s, j);
            int s1 = __shfl_sync(0xffffffffu, s, j + 1);
            int s2 = __shfl_sync(0xffffffffu, s, j + 2);
            int s3 = __shfl_sync(0xffffffffu, s, j + 3);
            float w0 = __shfl_sync(0xffffffffu, w, j);
            float w1 = __shfl_sync(0xffffffffu, w, j + 1);
            float w2 = __shfl_sync(0xffffffffu, w, j + 2);
            float w3 = __shfl_sync(0xffffffffu, w, j + 3);
            float4 v0 = *(const float4*)(feat + (size_t)s0 * 128 + lane * 4);
            float4 v1 = *(const float4*)(feat + (size_t)s1 * 128 + lane * 4);
            float4 v2 = *(const float4*)(feat + (size_t)s2 * 128 + lane * 4);
            float4 v3 = *(const float4*)(feat + (size_t)s3 * 128 + lane * 4);
            acc.x = fmaf(w0, v0.x, acc.x); acc.y = fmaf(w0, v0.y, acc.y);
            acc.z = fmaf(w0, v0.z, acc.z); acc.w = fmaf(w0, v0.w, acc.w);
            acc.x = fmaf(w1, v1.x, acc.x); acc.y = fmaf(w1, v1.y, acc.y);
            acc.z = fmaf(w1, v1.z, acc.z); acc.w = fmaf(w1, v1.w, acc.w);
            acc.x = fmaf(w2, v2.x, acc.x); acc.y = fmaf(w2, v2.y, acc.y);
            acc.z = fmaf(w2, v2.z, acc.z); acc.w = fmaf(w2, v2.w, acc.w);
            acc.x = fmaf(w3, v3.x, acc.x); acc.y = fmaf(w3, v3.y, acc.y);
            acc.z = fmaf(w3, v3.z, acc.z); acc.w = fmaf(w3, v3.w, acc.w);
        }
        for (; j < ne; j++) {
            int   sj = __shfl_sync(0xffffffffu, s, j);
            float wj = __shfl_sync(0xffffffffu, w, j);
            float4 v = *(const float4*)(feat + (size_t)sj * 128 + lane * 4);
            acc.x = fmaf(wj, v.x, acc.x);
            acc.y = fmaf(wj, v.y, acc.y);
            acc.z = fmaf(wj, v.z, acc.z);
            acc.w = fmaf(wj, v.w, acc.w);
        }
    }
    acc.x *= dn; acc.y *= dn; acc.z *= dn; acc.w *= dn;

    float f[4] = {acc.x, acc.y, acc.z, acc.w};
    __nv_bfloat16 hi[4], lo[4];
    #pragma unroll
    for (int j2 = 0; j2 < 4; j2++) {
        hi[j2] = __float2bfloat16(f[j2]);
        lo[j2] = __float2bfloat16(f[j2] - __bfloat162float(hi[j2]));
    }
    size_t o = (size_t)n * 128 + lane * 4;
    __nv_bfloat162 h0; h0.x = hi[0]; h0.y = hi[1];
    __nv_bfloat162 h1; h1.x = hi[2]; h1.y = hi[3];
    __nv_bfloat162 l0; l0.x = lo[0]; l0.y = lo[1];
    __nv_bfloat162 l1; l1.x = lo[2]; l1.y = lo[3];
    *(__nv_bfloat162*)(ohi + o)     = h0;
    *(__nv_bfloat162*)(ohi + o + 2) = h1;
    *(__nv_bfloat162*)(olo + o)     = l0;
    *(__nv_bfloat162*)(olo + o + 2) = l1;
}

// ---------------- final aggregation from fp16 rows, fp32 out, MLP-4 unrolled ----------------
__global__ void __launch_bounds__(256) k_agg_f16(
    const __half* __restrict__ feat, float* __restrict__ outp,
    const float* __restrict__ bias)
{
    int n = (blockIdx.x * blockDim.x + threadIdx.x) >> 5;
    if (n >= N_NODES) return;
    int lane = threadIdx.x & 31;
    int start = g_rowstart[n];
    int end   = g_rowstart[n + 1];
    float dn = g_dinv[n];

    uint2 raw = *(const uint2*)(feat + (size_t)n * 128 + lane * 4);
    float2 s01 = __half22float2(*(__half2*)&raw.x);
    float2 s23 = __half22float2(*(__half2*)&raw.y);
    float4 acc;
    acc.x = dn * s01.x; acc.y = dn * s01.y;
    acc.z = dn * s23.x; acc.w = dn * s23.y;

    for (int r = start; r < end; r += 32) {
        int ne = min(32, end - r);
        int s = 0; float w = 0.f;
        if (lane < ne) { s = g_csr[r + lane]; w = g_dinv[s]; }
        int j = 0;
        for (; j + 4 <= ne; j += 4) {
            int s0 = __shfl_sync(0xffffffffu, s, j);
            int s1 = __shfl_sync(0xffffffffu, s, j + 1);
            int s2 = __shfl_sync(0xffffffffu, s, j + 2);
            int s3 = __shfl_sync(0xffffffffu, s, j + 3);
            float w0 = __shfl_sync(0xffffffffu, w, j);
            float w1 = __shfl_sync(0xffffffffu, w, j + 1);
            float w2 = __shfl_sync(0xffffffffu, w, j + 2);
            float w3 = __shfl_sync(0xffffffffu, w, j + 3);
            uint2 r0 = *(const uint2*)(feat + (size_t)s0 * 128 + lane * 4);
            uint2 r1 = *(const uint2*)(feat + (size_t)s1 * 128 + lane * 4);
            uint2 r2 = *(const uint2*)(feat + (size_t)s2 * 128 + lane * 4);
            uint2 r3 = *(const uint2*)(feat + (size_t)s3 * 128 + lane * 4);
            float2 a0 = __half22float2(*(__half2*)&r0.x), b0 = __half22float2(*(__half2*)&r0.y);
            float2 a1 = __half22float2(*(__half2*)&r1.x), b1 = __half22float2(*(__half2*)&r1.y);
            float2 a2 = __half22float2(*(__half2*)&r2.x), b2 = __half22float2(*(__half2*)&r2.y);
            float2 a3 = __half22float2(*(__half2*)&r3.x), b3 = __half22float2(*(__half2*)&r3.y);
            acc.x = fmaf(w0, a0.x, acc.x); acc.y = fmaf(w0, a0.y, acc.y);
            acc.z = fmaf(w0, b0.x, acc.z); acc.w = fmaf(w0, b0.y, acc.w);
            acc.x = fmaf(w1, a1.x, acc.x); acc.y = fmaf(w1, a1.y, acc.y);
            acc.z = fmaf(w1, b1.x, acc.z); acc.w = fmaf(w1, b1.y, acc.w);
            acc.x = fmaf(w2, a2.x, acc.x); acc.y = fmaf(w2, a2.y, acc.y);
            acc.z = fmaf(w2, b2.x, acc.z); acc.w = fmaf(w2, b2.y, acc.w);
            acc.x = fmaf(w3, a3.x, acc.x); acc.y = fmaf(w3, a3.y, acc.y);
            acc.z = fmaf(w3, b3.x, acc.z); acc.w = fmaf(w3, b3.y, acc.w);
        }
        for (; j < ne; j++) {
            int   sj = __shfl_sync(0xffffffffu, s, j);
            float wj = __shfl_sync(0xffffffffu, w, j);
            uint2 rv = *(const uint2*)(feat + (size_t)sj * 128 + lane * 4);
            float2 v01 = __half22float2(*(__half2*)&rv.x);
            float2 v23 = __half22float2(*(__half2*)&rv.y);
            acc.x = fmaf(wj, v01.x, acc.x);
            acc.y = fmaf(wj, v01.y, acc.y);
            acc.z = fmaf(wj, v23.x, acc.z);
            acc.w = fmaf(wj, v23.y, acc.w);
        }
    }
    float4 b = *(const float4*)(bias + lane * 4);
    acc.x = fmaf(dn, acc.x, b.x);
    acc.y = fmaf(dn, acc.y, b.y);
    acc.z = fmaf(dn, acc.z, b.z);
    acc.w = fmaf(dn, acc.w, b.w);
    *(float4*)(outp + (size_t)n * 128 + lane * 4) = acc;
}

// ---------------- bf16 mma.sync GEMM with cp.async 2-stage pipeline (R13 verbatim) ----------------
// OUTMODE: 1 = bf16 hi/lo, 2 = fp16
template<int N, int K, int OUTMODE, bool RELU, bool BIAS>
__global__ void __launch_bounds__(256) k_mma(
    const __nv_bfloat16* __restrict__ Ahi, const __nv_bfloat16* __restrict__ Alo,
    const __nv_bfloat16* __restrict__ Wth, const __nv_bfloat16* __restrict__ Wtl,
    const float* __restrict__ bias,
    __half* __restrict__ Ch, __nv_bfloat16* __restrict__ Chi, __nv_bfloat16* __restrict__ Clo,
    int M)
{
    constexpr int STG = 40960;
    constexpr int O_AH = 0, O_AL = 10240, O_WH = 20480, O_WL = 30720;
    constexpr int NK = K / 32;

    extern __shared__ __align__(16) char smem[];
    uint32_t su = smem_u32(smem);

    int tid = threadIdx.x, lane = tid & 31, wid = tid >> 5;
    int wm = wid >> 1, wn = wid & 1;
    int bm = blockIdx.x * 128, bn = blockIdx.y * 128;

    float acc[2][8][4];
    #pragma unroll
    for (int s = 0; s < 2; s++)
        #pragma unroll
        for (int p = 0; p < 8; p++)
            #pragma unroll
            for (int q = 0; q < 4; q++) acc[s][p][q] = 0.f;

    int a_r    = lane & 15;
    int a_half = lane >> 4;
    int b_nr   = ((lane >> 4) << 3) + (lane & 7);
    int b_half = (lane >> 3) & 1;

    auto load_stage = [&](int st, int k0) {
        uint32_t base = su + st * STG;
        #pragma unroll
        for (int ii = 0; ii < 2; ii++) {
            int i = tid + ii * 256;
            int row = i >> 2, c = i & 3;
            uint32_t soff = (uint32_t)row * 80 + c * 16;
            int grow = bm + row;
            uint32_t pA = (grow < M) ? 16u : 0u;
            int crow = grow < M ? grow : (M - 1);
            cpa16(base + O_AH + soff, Ahi + (size_t)crow * K + k0 + c * 8, pA);
            cpa16(base + O_AL + soff, Alo + (size_t)crow * K + k0 + c * 8, pA);
            int nrow = bn + row;
            cpa16(base + O_WH + soff, Wth + (size_t)nrow * K + k0 + c * 8, 16u);
            cpa16(base + O_WL + soff, Wtl + (size_t)nrow * K + k0 + c * 8, 16u);
        }
        cpa_commit();
    };

    load_stage(0, 0);

    for (int k0i = 0; k0i < NK; k0i++) {
        int buf = k0i & 1;
        if (k0i + 1 < NK) {
            load_stage(buf ^ 1, (k0i + 1) * 32);
            cpa_wait<1>();
        } else {
            cpa_wait<0>();
        }
        __syncthreads();

        uint32_t bA = su + buf * STG;
        #pragma unroll
        for (int kk = 0; kk < 32; kk += 16) {
            uint32_t ah[2][4], al[2][4];
            #pragma unroll
            for (int s = 0; s < 2; s++) {
                int row = wm * 32 + s * 16 + a_r;
                int kc = (kk >> 3) + a_half;
                uint32_t off = (uint32_t)row * 80 + kc * 16;
                ldsm4(ah[s], bA + O_AH + off);
                ldsm4(al[s], bA + O_AL + off);
            }
            uint32_t bh[4][4], bl[4][4];
            #pragma unroll
            for (int p = 0; p < 4; p++) {
                int row = wn * 64 + p * 16 + b_nr;
                int kc = (kk >> 3) + b_half;
                uint32_t off = (uint32_t)row * 80 + kc * 16;
                ldsm4(bh[p], bA + O_WH + off);
                ldsm4(bl[p], bA + O_WL + off);
            }
            #pragma unroll
            for (int s = 0; s < 2; s++)
                #pragma unroll
                for (int p = 0; p < 4; p++)
                    #pragma unroll
                    for (int t = 0; t < 2; t++) {
                        float* c = acc[s][p * 2 + t];
                        mma16816(c, ah[s], bh[p][t * 2], bh[p][t * 2 + 1]);
                        mma16816(c, ah[s], bl[p][t * 2], bl[p][t * 2 + 1]);
                        mma16816(c, al[s], bh[p][t * 2], bh[p][t * 2 + 1]);
                    }
        }
        __syncthreads();
    }

    int g = lane >> 2, t = lane & 3;
    #pragma unroll
    for (int s = 0; s < 2; s++) {
        int r0 = bm + wm * 32 + s * 16 + g;
        #pragma unroll
        for (int p8 = 0; p8 < 8; p8++) {
            int col = bn + wn * 64 + p8 * 8 + t * 2;
            float v0 = acc[s][p8][0], v1 = acc[s][p8][1];
            float v2 = acc[s][p8][2], v3 = acc[s][p8][3];
            if (BIAS) {
                float b0 = bias[col], b1 = bias[col + 1];
                v0 += b0; v1 += b1; v2 += b0; v3 += b1;
            }
            if (RELU) {
                v0 = fmaxf(v0, 0.f); v1 = fmaxf(v1, 0.f);
                v2 = fmaxf(v2, 0.f); v3 = fmaxf(v3, 0.f);
            }
            if (OUTMODE == 1) {
                if (r0 < M) {
                    __nv_bfloat16 h0 = __float2bfloat16(v0), h1 = __float2bfloat16(v1);
                    __nv_bfloat162 hh; hh.x = h0; hh.y = h1;
                    __nv_bfloat162 ll;
                    ll.x = __float2bfloat16(v0 - __bfloat162float(h0));
                    ll.y = __float2bfloat16(v1 - __bfloat162float(h1));
                    *(__nv_bfloat162*)(Chi + (size_t)r0 * N + col) = hh;
                    *(__nv_bfloat162*)(Clo + (size_t)r0 * N + col) = ll;
                }
                if (r0 + 8 < M) {
                    __nv_bfloat16 h0 = __float2bfloat16(v2), h1 = __float2bfloat16(v3);
                    __nv_bfloat162 hh; hh.x = h0; hh.y = h1;
                    __nv_bfloat162 ll;
                    ll.x = __float2bfloat16(v2 - __bfloat162float(h0));
                    ll.y = __float2bfloat16(v3 - __bfloat162float(h1));
                    *(__nv_bfloat162*)(Chi + (size_t)(r0 + 8) * N + col) = hh;
                    *(__nv_bfloat162*)(Clo + (size_t)(r0 + 8) * N + col) = ll;
                }
            } else if (OUTMODE == 2) {
                if (r0 < M)
                    *(__half2*)(Ch + (size_t)r0 * N + col) = __floats2half2_rn(v0, v1);
                if (r0 + 8 < M)
                    *(__half2*)(Ch + (size_t)(r0 + 8) * N + col) = __floats2half2_rn(v2, v3);
            }
        }
    }
}

// ---------------- launch ----------------
extern "C" void kernel_launch(void* const* d_in, const int* in_sizes, int n_in,
                              void* d_out, int out_size)
{
    const float* x  = (const float*)d_in[0];
    const int*   ei = (const int*)  d_in[1];
    const float* W1 = (const float*)d_in[2];
    const float* b1 = (const float*)d_in[3];
    const float* W2 = (const float*)d_in[4];
    const float* b2 = (const float*)d_in[5];
    float* out = (float*)d_out;

    void *p_deg, *p_pf, *p_ahi, *p_alo, *p_hhi, *p_hlo, *p_w1h, *p_w1l, *p_w2h, *p_w2l;
    cudaGetSymbolAddress(&p_deg, g_deg);
    cudaGetSymbolAddress(&p_pf,  g_pf16);
    cudaGetSymbolAddress(&p_ahi, g_ahi);
    cudaGetSymbolAddress(&p_alo, g_alo);
    cudaGetSymbolAddress(&p_hhi, g_hhi);
    cudaGetSymbolAddress(&p_hlo, g_hlo);
    cudaGetSymbolAddress(&p_w1h, g_w1h);
    cudaGetSymbolAddress(&p_w1l, g_w1l);
    cudaGetSymbolAddress(&p_w2h, g_w2h);
    cudaGetSymbolAddress(&p_w2l, g_w2l);

    const int T = 256;
    const int SMEM_SZ = 81920;

    cudaFuncSetAttribute(k_mma<HID_CH, IN_CH, 1, true, true>,
                         cudaFuncAttributeMaxDynamicSharedMemorySize, SMEM_SZ);
    cudaFuncSetAttribute(k_mma<OUT_CH, HID_CH, 2, false, false>,
                         cudaFuncAttributeMaxDynamicSharedMemorySize, SMEM_SZ);

    // CSR build + weight prep (fused: 4 nodes total)
    cudaMemsetAsync(p_deg, 0, N_NODES * sizeof(int));
    k_count_prep<<<CD_BLOCKS + PW_BLOCKS, T>>>(ei, W1, W2);
    k_scan_fused<<<SCAN_NB, SCAN_BLK>>>();
    k_fill_csr<<<(N_EDGES + T - 1) / T, T>>>(ei);

    int agrid = (N_NODES * 32 + T - 1) / T;   // one warp per node
    int mgrid = (N_NODES + 127) / 128;        // 391 M-blocks

    // ---- layer 1: gather-aggregate -> bf16 hi/lo, then tensor GEMM ----
    k_agg_bf16<<<agrid, T>>>(x, (__nv_bfloat16*)p_ahi, (__nv_bfloat16*)p_alo);
    {
        dim3 grid(mgrid, HID_CH / 128);
        k_mma<HID_CH, IN_CH, 1, true, true><<<grid, 256, SMEM_SZ>>>(
            (const __nv_bfloat16*)p_ahi, (const __nv_bfloat16*)p_alo,
            (const __nv_bfloat16*)p_w1h, (const __nv_bfloat16*)p_w1l,
            b1, nullptr, (__nv_bfloat16*)p_hhi, (__nv_bfloat16*)p_hlo, N_NODES);
    }

    // ---- layer 2: tensor GEMM (fp16 out), then gather-aggregate + bias ----
    {
        dim3 grid(mgrid, OUT_CH / 128);
        k_mma<OUT_CH, HID_CH, 2, false, false><<<grid, 256, SMEM_SZ>>>(
            (const __nv_bfloat16*)p_hhi, (const __nv_bfloat16*)p_hlo,
            (const __nv_bfloat16*)p_w2h, (const __nv_bfloat16*)p_w2l,
            nullptr, (__half*)p_pf, nullptr, nullptr, N_NODES);
    }
    k_agg_f16<<<agrid, T>>>((const __half*)p_pf, out, b2);
}

// round 16
// speedup vs baseline: 2.6686x; 1.1019x over previous
#include <cuda_runtime.h>
#include <cuda_bf16.h>
#include <cuda_fp16.h>
#include <math.h>
#include <cstdint>

#define N_NODES 50000
#define N_EDGES 800000
#define IN_CH   128
#define HID_CH  256
#define OUT_CH  128

#define SCAN_BLK 1024
#define SCAN_NB  ((N_NODES + SCAN_BLK - 1) / SCAN_BLK)   // 49
#define CD_BLOCKS ((N_EDGES + 255) / 256)                // 3125
#define PW_BLOCKS ((2 * 32768 + 255) / 256)              // 256
#define PS_BLOCKS ((N_NODES * 32 + 255) / 256)           // 6250

// ---------------- scratch (__device__ globals; no allocation allowed) ----------------
__device__ int   g_deg[N_NODES];
__device__ float g_dinv[N_NODES];
__device__ int   g_rowstart[N_NODES + 1];
__device__ int   g_fill[N_NODES];
__device__ int   g_csr[N_EDGES];
__device__ int   g_bsum[SCAN_NB];
__device__ int   g_bflag[SCAN_NB];
__device__ __half g_xs16[(size_t)N_NODES * IN_CH];           // dinv[n]*x[n] (fp16)
__device__ __half g_ps16[(size_t)N_NODES * OUT_CH];          // dinv[n]*(h@W2)[n] (fp16)
__device__ __nv_bfloat16 g_ahi[(size_t)N_NODES * IN_CH];
__device__ __nv_bfloat16 g_alo[(size_t)N_NODES * IN_CH];
__device__ __nv_bfloat16 g_hhi[(size_t)N_NODES * HID_CH];
__device__ __nv_bfloat16 g_hlo[(size_t)N_NODES * HID_CH];
__device__ __nv_bfloat16 g_w1h[HID_CH * IN_CH];
__device__ __nv_bfloat16 g_w1l[HID_CH * IN_CH];
__device__ __nv_bfloat16 g_w2h[OUT_CH * HID_CH];
__device__ __nv_bfloat16 g_w2l[OUT_CH * HID_CH];

// ---------------- helpers ----------------
__device__ __forceinline__ uint32_t smem_u32(const void* p) {
    uint32_t a;
    asm("{ .reg .u64 t; cvta.to.shared.u64 t, %1; cvt.u32.u64 %0, t; }" : "=r"(a) : "l"(p));
    return a;
}
__device__ __forceinline__ void ldsm4(uint32_t* r, uint32_t addr) {
    asm volatile("ldmatrix.sync.aligned.m8n8.x4.shared.b16 {%0,%1,%2,%3}, [%4];"
        : "=r"(r[0]), "=r"(r[1]), "=r"(r[2]), "=r"(r[3]) : "r"(addr));
}
__device__ __forceinline__ void mma16816(float* c, const uint32_t* a, uint32_t b0, uint32_t b1) {
    asm volatile("mma.sync.aligned.m16n8k16.row.col.f32.bf16.bf16.f32 "
        "{%0,%1,%2,%3}, {%4,%5,%6,%7}, {%8,%9}, {%0,%1,%2,%3};"
        : "+f"(c[0]), "+f"(c[1]), "+f"(c[2]), "+f"(c[3])
        : "r"(a[0]), "r"(a[1]), "r"(a[2]), "r"(a[3]), "r"(b0), "r"(b1));
}
__device__ __forceinline__ void cpa16(uint32_t saddr, const void* gaddr, uint32_t srcsz) {
    asm volatile("cp.async.ca.shared.global [%0], [%1], 16, %2;"
                 :: "r"(saddr), "l"(gaddr), "r"(srcsz) : "memory");
}
__device__ __forceinline__ void cpa_commit() {
    asm volatile("cp.async.commit_group;" ::: "memory");
}
template<int N_>
__device__ __forceinline__ void cpa_wait() {
    asm volatile("cp.async.wait_group %0;" :: "n"(N_) : "memory");
}

// ---------------- fused: degree count + weight prep + scan-flag zero ----------------
__global__ void k_count_prep(const int* __restrict__ ei,
                             const float* __restrict__ W1, const float* __restrict__ W2) {
    int b = blockIdx.x, tid = threadIdx.x;
    if (b == 0 && tid < SCAN_NB) g_bflag[tid] = 0;
    if (b < CD_BLOCKS) {
        int i = b * 256 + tid;
        if (i < N_EDGES) atomicAdd(&g_deg[ei[N_EDGES + i]], 1);
    } else {
        int idx = (b - CD_BLOCKS) * 256 + tid;
        if (idx >= 2 * 32768) return;
        int which = idx >> 15;
        int e = idx & 32767;
        if (which == 0) {
            int n = e & 255, k = e >> 8;
            float w = W1[k * 256 + n];
            __nv_bfloat16 hi = __float2bfloat16(w);
            __nv_bfloat16 lo = __float2bfloat16(w - __bfloat162float(hi));
            g_w1h[n * 128 + k] = hi;
            g_w1l[n * 128 + k] = lo;
        } else {
            int n = e & 127, k = e >> 7;
            float w = W2[k * 128 + n];
            __nv_bfloat16 hi = __float2bfloat16(w);
            __nv_bfloat16 lo = __float2bfloat16(w - __bfloat162float(hi));
            g_w2h[n * 256 + k] = hi;
            g_w2l[n * 256 + k] = lo;
        }
    }
}

// ---------------- single-kernel scan with decoupled lookback (R14 verbatim) ----------------
__global__ void __launch_bounds__(SCAN_BLK) k_scan_fused() {
    __shared__ int wsum[32];
    __shared__ int s_pref;
    __shared__ int s_par[2];
    int tid = threadIdx.x, lane = tid & 31, wid = tid >> 5;
    int bid = blockIdx.x;
    int i = bid * SCAN_BLK + tid;
    int d = (i < N_NODES) ? g_deg[i] : 0;
    int v = d;
    #pragma unroll
    for (int o = 1; o < 32; o <<= 1) {
        int t = __shfl_up_sync(0xffffffffu, v, o);
        if (lane >= o) v += t;
    }
    if (lane == 31) wsum[wid] = v;
    __syncthreads();
    if (wid == 0) {
        int w = wsum[lane];
        #pragma unroll
        for (int o = 1; o < 32; o <<= 1) {
            int t = __shfl_up_sync(0xffffffffu, w, o);
            if (lane >= o) w += t;
        }
        wsum[lane] = w;
    }
    __syncthreads();
    int excl = (wid ? wsum[wid - 1] : 0) + v - d;

    if (tid == 0) {
        g_bsum[bid] = wsum[31];
        __threadfence();
        atomicExch(&g_bflag[bid], 1);
    }
    int pv = 0;
    if (tid < 64) {
        if (tid < bid) {
            while (atomicAdd(&g_bflag[tid], 0) == 0) {}
            pv = g_bsum[tid];
        }
        #pragma unroll
        for (int o = 16; o; o >>= 1) pv += __shfl_down_sync(0xffffffffu, pv, o);
        if ((tid & 31) == 0) s_par[tid >> 5] = pv;
    }
    __syncthreads();
    if (tid == 0) s_pref = s_par[0] + s_par[1];
    __syncthreads();
    int pref = s_pref;

    if (i < N_NODES) {
        int r = excl + pref;
        g_rowstart[i] = r;
        g_fill[i] = r;
        g_dinv[i] = rsqrtf((float)d + 1.0f);
    }
    if (i == 0) g_rowstart[N_NODES] = N_EDGES;
}

// ---------------- fused: CSR fill + pre-scaled fp16 x rows ----------------
__global__ void k_fill_prescale(const int* __restrict__ ei, const float* __restrict__ x) {
    int b = blockIdx.x, tid = threadIdx.x;
    if (b < CD_BLOCKS) {
        int i = b * 256 + tid;
        if (i < N_EDGES) {
            int src = ei[i];
            int dst = ei[N_EDGES + i];
            int pos = atomicAdd(&g_fill[dst], 1);
            g_csr[pos] = src;
        }
    } else {
        int idx = (b - CD_BLOCKS) * 256 + tid;   // over N_NODES*32 float4 lanes
        if (idx >= N_NODES * 32) return;
        int row = idx >> 5;
        float dn = g_dinv[row];
        float4 v = *(const float4*)(x + (size_t)idx * 4);
        uint2 o;
        *(__half2*)&o.x = __floats2half2_rn(dn * v.x, dn * v.y);
        *(__half2*)&o.y = __floats2half2_rn(dn * v.z, dn * v.w);
        *(uint2*)(g_xs16 + (size_t)idx * 4) = o;
    }
}

// ---------------- layer-1 aggregation: unweighted fp16 sum -> bf16 hi/lo ----------------
// t1[n] = dinv[n] * ( xs[n] + sum_{s} xs[s] )
__global__ void __launch_bounds__(256) k_agg1(
    const __half* __restrict__ xs,
    __nv_bfloat16* __restrict__ ohi, __nv_bfloat16* __restrict__ olo)
{
    int n = (blockIdx.x * blockDim.x + threadIdx.x) >> 5;
    if (n >= N_NODES) return;
    int lane = threadIdx.x & 31;
    int start = g_rowstart[n];
    int end   = g_rowstart[n + 1];
    float dn = g_dinv[n];

    uint2 raw = *(const uint2*)(xs + (size_t)n * 128 + lane * 4);
    float2 s01 = __half22float2(*(__half2*)&raw.x);
    float2 s23 = __half22float2(*(__half2*)&raw.y);
    float4 acc = make_float4(s01.x, s01.y, s23.x, s23.y);

    for (int r = start; r < end; r += 32) {
        int ne = min(32, end - r);
        int s = 0;
        if (lane < ne) s = g_csr[r + lane];
        int j = 0;
        for (; j + 4 <= ne; j += 4) {
            int s0 = __shfl_sync(0xffffffffu, s, j);
            int s1 = __shfl_sync(0xffffffffu, s, j + 1);
            int s2 = __shfl_sync(0xffffffffu, s, j + 2);
            int s3 = __shfl_sync(0xffffffffu, s, j + 3);
            uint2 r0 = *(const uint2*)(xs + (size_t)s0 * 128 + lane * 4);
            uint2 r1 = *(const uint2*)(xs + (size_t)s1 * 128 + lane * 4);
            uint2 r2 = *(const uint2*)(xs + (size_t)s2 * 128 + lane * 4);
            uint2 r3 = *(const uint2*)(xs + (size_t)s3 * 128 + lane * 4);
            float2 a0 = __half22float2(*(__half2*)&r0.x), b0 = __half22float2(*(__half2*)&r0.y);
            float2 a1 = __half22float2(*(__half2*)&r1.x), b1 = __half22float2(*(__half2*)&r1.y);
            float2 a2 = __half22float2(*(__half2*)&r2.x), b2 = __half22float2(*(__half2*)&r2.y);
            float2 a3 = __half22float2(*(__half2*)&r3.x), b3 = __half22float2(*(__half2*)&r3.y);
            acc.x += a0.x + a1.x; acc.y += a0.y + a1.y;
            acc.z += b0.x + b1.x; acc.w += b0.y + b1.y;
            acc.x += a2.x + a3.x; acc.y += a2.y + a3.y;
            acc.z += b2.x + b3.x; acc.w += b2.y + b3.y;
        }
        for (; j < ne; j++) {
            int sj = __shfl_sync(0xffffffffu, s, j);
            uint2 rv = *(const uint2*)(xs + (size_t)sj * 128 + lane * 4);
            float2 v01 = __half22float2(*(__half2*)&rv.x);
            float2 v23 = __half22float2(*(__half2*)&rv.y);
            acc.x += v01.x; acc.y += v01.y;
            acc.z += v23.x; acc.w += v23.y;
        }
    }
    float f[4] = {dn * acc.x, dn * acc.y, dn * acc.z, dn * acc.w};
    __nv_bfloat16 hi[4], lo[4];
    #pragma unroll
    for (int j2 = 0; j2 < 4; j2++) {
        hi[j2] = __float2bfloat16(f[j2]);
        lo[j2] = __float2bfloat16(f[j2] - __bfloat162float(hi[j2]));
    }
    size_t o = (size_t)n * 128 + lane * 4;
    __nv_bfloat162 h0; h0.x = hi[0]; h0.y = hi[1];
    __nv_bfloat162 h1; h1.x = hi[2]; h1.y = hi[3];
    __nv_bfloat162 l0; l0.x = lo[0]; l0.y = lo[1];
    __nv_bfloat162 l1; l1.x = lo[2]; l1.y = lo[3];
    *(__nv_bfloat162*)(ohi + o)     = h0;
    *(__nv_bfloat162*)(ohi + o + 2) = h1;
    *(__nv_bfloat162*)(olo + o)     = l0;
    *(__nv_bfloat162*)(olo + o + 2) = l1;
}

// ---------------- final aggregation: unweighted fp16 sum -> fp32 out + bias ----------------
// out[n] = dinv[n] * ( ps[n] + sum_{s} ps[s] ) + b2
__global__ void __launch_bounds__(256) k_agg2(
    const __half* __restrict__ ps, float* __restrict__ outp,
    const float* __restrict__ bias)
{
    int n = (blockIdx.x * blockDim.x + threadIdx.x) >> 5;
    if (n >= N_NODES) return;
    int lane = threadIdx.x & 31;
    int start = g_rowstart[n];
    int end   = g_rowstart[n + 1];
    float dn = g_dinv[n];

    uint2 raw = *(const uint2*)(ps + (size_t)n * 128 + lane * 4);
    float2 s01 = __half22float2(*(__half2*)&raw.x);
    float2 s23 = __half22float2(*(__half2*)&raw.y);
    float4 acc = make_float4(s01.x, s01.y, s23.x, s23.y);

    for (int r = start; r < end; r += 32) {
        int ne = min(32, end - r);
        int s = 0;
        if (lane < ne) s = g_csr[r + lane];
        int j = 0;
        for (; j + 4 <= ne; j += 4) {
            int s0 = __shfl_sync(0xffffffffu, s, j);
            int s1 = __shfl_sync(0xffffffffu, s, j + 1);
            int s2 = __shfl_sync(0xffffffffu, s, j + 2);
            int s3 = __shfl_sync(0xffffffffu, s, j + 3);
            uint2 r0 = *(const uint2*)(ps + (size_t)s0 * 128 + lane * 4);
            uint2 r1 = *(const uint2*)(ps + (size_t)s1 * 128 + lane * 4);
            uint2 r2 = *(const uint2*)(ps + (size_t)s2 * 128 + lane * 4);
            uint2 r3 = *(const uint2*)(ps + (size_t)s3 * 128 + lane * 4);
            float2 a0 = __half22float2(*(__half2*)&r0.x), b0 = __half22float2(*(__half2*)&r0.y);
            float2 a1 = __half22float2(*(__half2*)&r1.x), b1 = __half22float2(*(__half2*)&r1.y);
            float2 a2 = __half22float2(*(__half2*)&r2.x), b2 = __half22float2(*(__half2*)&r2.y);
            float2 a3 = __half22float2(*(__half2*)&r3.x), b3 = __half22float2(*(__half2*)&r3.y);
            acc.x += a0.x + a1.x; acc.y += a0.y + a1.y;
            acc.z += b0.x + b1.x; acc.w += b0.y + b1.y;
            acc.x += a2.x + a3.x; acc.y += a2.y + a3.y;
            acc.z += b2.x + b3.x; acc.w += b2.y + b3.y;
        }
        for (; j < ne; j++) {
            int sj = __shfl_sync(0xffffffffu, s, j);
            uint2 rv = *(const uint2*)(ps + (size_t)sj * 128 + lane * 4);
            float2 v01 = __half22float2(*(__half2*)&rv.x);
            float2 v23 = __half22float2(*(__half2*)&rv.y);
            acc.x += v01.x; acc.y += v01.y;
            acc.z += v23.x; acc.w += v23.y;
        }
    }
    float4 b = *(const float4*)(bias + lane * 4);
    float4 o;
    o.x = fmaf(dn, acc.x, b.x);
    o.y = fmaf(dn, acc.y, b.y);
    o.z = fmaf(dn, acc.z, b.z);
    o.w = fmaf(dn, acc.w, b.w);
    *(float4*)(outp + (size_t)n * 128 + lane * 4) = o;
}

// ---------------- bf16 mma.sync GEMM with cp.async 2-stage pipeline ----------------
// OUTMODE: 1 = bf16 hi/lo, 2 = fp16 scaled by g_dinv[row]
template<int N, int K, int OUTMODE, bool RELU, bool BIAS>
__global__ void __launch_bounds__(256) k_mma(
    const __nv_bfloat16* __restrict__ Ahi, const __nv_bfloat16* __restrict__ Alo,
    const __nv_bfloat16* __restrict__ Wth, const __nv_bfloat16* __restrict__ Wtl,
    const float* __restrict__ bias,
    __half* __restrict__ Ch, __nv_bfloat16* __restrict__ Chi, __nv_bfloat16* __restrict__ Clo,
    int M)
{
    constexpr int STG = 40960;
    constexpr int O_AH = 0, O_AL = 10240, O_WH = 20480, O_WL = 30720;
    constexpr int NK = K / 32;

    extern __shared__ __align__(16) char smem[];
    uint32_t su = smem_u32(smem);

    int tid = threadIdx.x, lane = tid & 31, wid = tid >> 5;
    int wm = wid >> 1, wn = wid & 1;
    int bm = blockIdx.x * 128, bn = blockIdx.y * 128;

    float acc[2][8][4];
    #pragma unroll
    for (int s = 0; s < 2; s++)
        #pragma unroll
        for (int p = 0; p < 8; p++)
            #pragma unroll
            for (int q = 0; q < 4; q++) acc[s][p][q] = 0.f;

    int a_r    = lane & 15;
    int a_half = lane >> 4;
    int b_nr   = ((lane >> 4) << 3) + (lane & 7);
    int b_half = (lane >> 3) & 1;

    auto load_stage = [&](int st, int k0) {
        uint32_t base = su + st * STG;
        #pragma unroll
        for (int ii = 0; ii < 2; ii++) {
            int i = tid + ii * 256;
            int row = i >> 2, c = i & 3;
            uint32_t soff = (uint32_t)row * 80 + c * 16;
            int grow = bm + row;
            uint32_t pA = (grow < M) ? 16u : 0u;
            int crow = grow < M ? grow : (M - 1);
            cpa16(base + O_AH + soff, Ahi + (size_t)crow * K + k0 + c * 8, pA);
            cpa16(base + O_AL + soff, Alo + (size_t)crow * K + k0 + c * 8, pA);
            int nrow = bn + row;
            cpa16(base + O_WH + soff, Wth + (size_t)nrow * K + k0 + c * 8, 16u);
            cpa16(base + O_WL + soff, Wtl + (size_t)nrow * K + k0 + c * 8, 16u);
        }
        cpa_commit();
    };

    load_stage(0, 0);

    for (int k0i = 0; k0i < NK; k0i++) {
        int buf = k0i & 1;
        if (k0i + 1 < NK) {
            load_stage(buf ^ 1, (k0i + 1) * 32);
            cpa_wait<1>();
        } else {
            cpa_wait<0>();
        }
        __syncthreads();

        uint32_t bA = su + buf * STG;
        #pragma unroll
        for (int kk = 0; kk < 32; kk += 16) {
            uint32_t ah[2][4], al[2][4];
            #pragma unroll
            for (int s = 0; s < 2; s++) {
                int row = wm * 32 + s * 16 + a_r;
                int kc = (kk >> 3) + a_half;
                uint32_t off = (uint32_t)row * 80 + kc * 16;
                ldsm4(ah[s], bA + O_AH + off);
                ldsm4(al[s], bA + O_AL + off);
            }
            uint32_t bh[4][4], bl[4][4];
            #pragma unroll
            for (int p = 0; p < 4; p++) {
                int row = wn * 64 + p * 16 + b_nr;
                int kc = (kk >> 3) + b_half;
                uint32_t off = (uint32_t)row * 80 + kc * 16;
                ldsm4(bh[p], bA + O_WH + off);
                ldsm4(bl[p], bA + O_WL + off);
            }
            #pragma unroll
            for (int s = 0; s < 2; s++)
                #pragma unroll
                for (int p = 0; p < 4; p++)
                    #pragma unroll
                    for (int t = 0; t < 2; t++) {
                        float* c = acc[s][p * 2 + t];
                        mma16816(c, ah[s], bh[p][t * 2], bh[p][t * 2 + 1]);
                        mma16816(c, ah[s], bl[p][t * 2], bl[p][t * 2 + 1]);
                        mma16816(c, al[s], bh[p][t * 2], bh[p][t * 2 + 1]);
                    }
        }
        __syncthreads();
    }

    int g = lane >> 2, t = lane & 3;
    #pragma unroll
    for (int s = 0; s < 2; s++) {
        int r0 = bm + wm * 32 + s * 16 + g;
        #pragma unroll
        for (int p8 = 0; p8 < 8; p8++) {
            int col = bn + wn * 64 + p8 * 8 + t * 2;
            float v0 = acc[s][p8][0], v1 = acc[s][p8][1];
            float v2 = acc[s][p8][2], v3 = acc[s][p8][3];
            if (BIAS) {
                float b0 = bias[col], b1 = bias[col + 1];
                v0 += b0; v1 += b1; v2 += b0; v3 += b1;
            }
            if (RELU) {
                v0 = fmaxf(v0, 0.f); v1 = fmaxf(v1, 0.f);
                v2 = fmaxf(v2, 0.f); v3 = fmaxf(v3, 0.f);
            }
            if (OUTMODE == 1) {
                if (r0 < M) {
                    __nv_bfloat16 h0 = __float2bfloat16(v0), h1 = __float2bfloat16(v1);
                    __nv_bfloat162 hh; hh.x = h0; hh.y = h1;
                    __nv_bfloat162 ll;
                    ll.x = __float2bfloat16(v0 - __bfloat162float(h0));
                    ll.y = __float2bfloat16(v1 - __bfloat162float(h1));
                    *(__nv_bfloat162*)(Chi + (size_t)r0 * N + col) = hh;
                    *(__nv_bfloat162*)(Clo + (size_t)r0 * N + col) = ll;
                }
                if (r0 + 8 < M) {
                    __nv_bfloat16 h0 = __float2bfloat16(v2), h1 = __float2bfloat16(v3);
                    __nv_bfloat162 hh; hh.x = h0; hh.y = h1;
                    __nv_bfloat162 ll;
                    ll.x = __float2bfloat16(v2 - __bfloat162float(h0));
                    ll.y = __float2bfloat16(v3 - __bfloat162float(h1));
                    *(__nv_bfloat162*)(Chi + (size_t)(r0 + 8) * N + col) = hh;
                    *(__nv_bfloat162*)(Clo + (size_t)(r0 + 8) * N + col) = ll;
                }
            } else if (OUTMODE == 2) {
                if (r0 < M) {
                    float d0 = g_dinv[r0];
                    *(__half2*)(Ch + (size_t)r0 * N + col) = __floats2half2_rn(v0 * d0, v1 * d0);
                }
                if (r0 + 8 < M) {
                    float d1 = g_dinv[r0 + 8];
                    *(__half2*)(Ch + (size_t)(r0 + 8) * N + col) = __floats2half2_rn(v2 * d1, v3 * d1);
                }
            }
        }
    }
}

// ---------------- launch ----------------
extern "C" void kernel_launch(void* const* d_in, const int* in_sizes, int n_in,
                              void* d_out, int out_size)
{
    const float* x  = (const float*)d_in[0];
    const int*   ei = (const int*)  d_in[1];
    const float* W1 = (const float*)d_in[2];
    const float* b1 = (const float*)d_in[3];
    const float* W2 = (const float*)d_in[4];
    const float* b2 = (const float*)d_in[5];
    float* out = (float*)d_out;

    void *p_deg, *p_xs, *p_ps, *p_ahi, *p_alo, *p_hhi, *p_hlo, *p_w1h, *p_w1l, *p_w2h, *p_w2l;
    cudaGetSymbolAddress(&p_deg, g_deg);
    cudaGetSymbolAddress(&p_xs,  g_xs16);
    cudaGetSymbolAddress(&p_ps,  g_ps16);
    cudaGetSymbolAddress(&p_ahi, g_ahi);
    cudaGetSymbolAddress(&p_alo, g_alo);
    cudaGetSymbolAddress(&p_hhi, g_hhi);
    cudaGetSymbolAddress(&p_hlo, g_hlo);
    cudaGetSymbolAddress(&p_w1h, g_w1h);
    cudaGetSymbolAddress(&p_w1l, g_w1l);
    cudaGetSymbolAddress(&p_w2h, g_w2h);
    cudaGetSymbolAddress(&p_w2l, g_w2l);

    const int T = 256;
    const int SMEM_SZ = 81920;

    cudaFuncSetAttribute(k_mma<HID_CH, IN_CH, 1, true, true>,
                         cudaFuncAttributeMaxDynamicSharedMemorySize, SMEM_SZ);
    cudaFuncSetAttribute(k_mma<OUT_CH, HID_CH, 2, false, false>,
                         cudaFuncAttributeMaxDynamicSharedMemorySize, SMEM_SZ);

    // CSR build + weight prep + prescale
    cudaMemsetAsync(p_deg, 0, N_NODES * sizeof(int));
    k_count_prep<<<CD_BLOCKS + PW_BLOCKS, T>>>(ei, W1, W2);
    k_scan_fused<<<SCAN_NB, SCAN_BLK>>>();
    k_fill_prescale<<<CD_BLOCKS + PS_BLOCKS, T>>>(ei, x);

    int agrid = (N_NODES * 32 + T - 1) / T;   // one warp per node
    int mgrid = (N_NODES + 127) / 128;        // 391 M-blocks

    // ---- layer 1: unweighted gather of pre-scaled fp16 x, then tensor GEMM ----
    k_agg1<<<agrid, T>>>((const __half*)p_xs, (__nv_bfloat16*)p_ahi, (__nv_bfloat16*)p_alo);
    {
        dim3 grid(mgrid, HID_CH / 128);
        k_mma<HID_CH, IN_CH, 1, true, true><<<grid, 256, SMEM_SZ>>>(
            (const __nv_bfloat16*)p_ahi, (const __nv_bfloat16*)p_alo,
            (const __nv_bfloat16*)p_w1h, (const __nv_bfloat16*)p_w1l,
            b1, nullptr, (__nv_bfloat16*)p_hhi, (__nv_bfloat16*)p_hlo, N_NODES);
    }

    // ---- layer 2: tensor GEMM (fp16 out, pre-scaled by dinv), then unweighted gather ----
    {
        dim3 grid(mgrid, OUT_CH / 128);
        k_mma<OUT_CH, HID_CH, 2, false, false><<<grid, 256, SMEM_SZ>>>(
            (const __nv_bfloat16*)p_hhi, (const __nv_bfloat16*)p_hlo,
            (const __nv_bfloat16*)p_w2h, (const __nv_bfloat16*)p_w2l,
            nullptr, (__half*)p_ps, nullptr, nullptr, N_NODES);
    }
    k_agg2<<<agrid, T>>>((const __half*)p_ps, out, b2);
}

// round 17
// speedup vs baseline: 3.6153x; 1.3548x over previous
#include <cuda_runtime.h>
#include <cuda_bf16.h>
#include <cuda_fp16.h>
#include <math.h>
#include <cstdint>

#define N_NODES 50000
#define N_EDGES 800000
#define IN_CH   128
#define HID_CH  256
#define OUT_CH  128

#define SCAN_BLK 1024
#define SCAN_NB  ((N_NODES + SCAN_BLK - 1) / SCAN_BLK)   // 49
#define CD_BLOCKS ((N_EDGES + 255) / 256)                // 3125
#define PW_BLOCKS ((2 * 32768 + 255) / 256)              // 256
#define PS_BLOCKS ((N_NODES * 32 + 255) / 256)           // 6250

// ---------------- scratch (__device__ globals; no allocation allowed) ----------------
__device__ int   g_deg[N_NODES];
__device__ float g_dinv[N_NODES];
__device__ int   g_rowstart[N_NODES + 1];
__device__ int   g_fill[N_NODES];
__device__ int   g_csr[N_EDGES];
__device__ int   g_bsum[SCAN_NB];
__device__ int   g_bflag[SCAN_NB];
__device__ __half g_xs16[(size_t)N_NODES * IN_CH];   // dinv[n]*x[n]        (fp16)
__device__ __half g_t1 [(size_t)N_NODES * IN_CH];    // aggregated layer-1 A (fp16)
__device__ __half g_h  [(size_t)N_NODES * HID_CH];   // relu hidden          (fp16)
__device__ __half g_ps16[(size_t)N_NODES * OUT_CH];  // dinv[n]*(h@W2)[n]    (fp16)
__device__ __half g_w1 [HID_CH * IN_CH];             // W1^T [n][k] fp16
__device__ __half g_w2 [OUT_CH * HID_CH];            // W2^T [n][k] fp16

// ---------------- helpers ----------------
__device__ __forceinline__ uint32_t smem_u32(const void* p) {
    uint32_t a;
    asm("{ .reg .u64 t; cvta.to.shared.u64 t, %1; cvt.u32.u64 %0, t; }" : "=r"(a) : "l"(p));
    return a;
}
__device__ __forceinline__ void ldsm4(uint32_t* r, uint32_t addr) {
    asm volatile("ldmatrix.sync.aligned.m8n8.x4.shared.b16 {%0,%1,%2,%3}, [%4];"
        : "=r"(r[0]), "=r"(r[1]), "=r"(r[2]), "=r"(r[3]) : "r"(addr));
}
__device__ __forceinline__ void mma16816h(float* c, const uint32_t* a, uint32_t b0, uint32_t b1) {
    asm volatile("mma.sync.aligned.m16n8k16.row.col.f32.f16.f16.f32 "
        "{%0,%1,%2,%3}, {%4,%5,%6,%7}, {%8,%9}, {%0,%1,%2,%3};"
        : "+f"(c[0]), "+f"(c[1]), "+f"(c[2]), "+f"(c[3])
        : "r"(a[0]), "r"(a[1]), "r"(a[2]), "r"(a[3]), "r"(b0), "r"(b1));
}
__device__ __forceinline__ void cpa16(uint32_t saddr, const void* gaddr, uint32_t srcsz) {
    asm volatile("cp.async.ca.shared.global [%0], [%1], 16, %2;"
                 :: "r"(saddr), "l"(gaddr), "r"(srcsz) : "memory");
}
__device__ __forceinline__ void cpa_commit() {
    asm volatile("cp.async.commit_group;" ::: "memory");
}
template<int N_>
__device__ __forceinline__ void cpa_wait() {
    asm volatile("cp.async.wait_group %0;" :: "n"(N_) : "memory");
}

// ---------------- fused: degree count + weight prep (fp16) + scan-flag zero ----------------
__global__ void k_count_prep(const int* __restrict__ ei,
                             const float* __restrict__ W1, const float* __restrict__ W2) {
    int b = blockIdx.x, tid = threadIdx.x;
    if (b == 0 && tid < SCAN_NB) g_bflag[tid] = 0;
    if (b < CD_BLOCKS) {
        int i = b * 256 + tid;
        if (i < N_EDGES) atomicAdd(&g_deg[ei[N_EDGES + i]], 1);
    } else {
        int idx = (b - CD_BLOCKS) * 256 + tid;
        if (idx >= 2 * 32768) return;
        int which = idx >> 15;
        int e = idx & 32767;
        if (which == 0) {
            int n = e & 255, k = e >> 8;            // n < 256, k < 128
            g_w1[n * 128 + k] = __float2half(W1[k * 256 + n]);
        } else {
            int n = e & 127, k = e >> 7;            // n < 128, k < 256
            g_w2[n * 256 + k] = __float2half(W2[k * 128 + n]);
        }
    }
}

// ---------------- single-kernel scan with decoupled lookback (known good) ----------------
__global__ void __launch_bounds__(SCAN_BLK) k_scan_fused() {
    __shared__ int wsum[32];
    __shared__ int s_pref;
    __shared__ int s_par[2];
    int tid = threadIdx.x, lane = tid & 31, wid = tid >> 5;
    int bid = blockIdx.x;
    int i = bid * SCAN_BLK + tid;
    int d = (i < N_NODES) ? g_deg[i] : 0;
    int v = d;
    #pragma unroll
    for (int o = 1; o < 32; o <<= 1) {
        int t = __shfl_up_sync(0xffffffffu, v, o);
        if (lane >= o) v += t;
    }
    if (lane == 31) wsum[wid] = v;
    __syncthreads();
    if (wid == 0) {
        int w = wsum[lane];
        #pragma unroll
        for (int o = 1; o < 32; o <<= 1) {
            int t = __shfl_up_sync(0xffffffffu, w, o);
            if (lane >= o) w += t;
        }
        wsum[lane] = w;
    }
    __syncthreads();
    int excl = (wid ? wsum[wid - 1] : 0) + v - d;

    if (tid == 0) {
        g_bsum[bid] = wsum[31];
        __threadfence();
        atomicExch(&g_bflag[bid], 1);
    }
    int pv = 0;
    if (tid < 64) {
        if (tid < bid) {
            while (atomicAdd(&g_bflag[tid], 0) == 0) {}
            pv = g_bsum[tid];
        }
        #pragma unroll
        for (int o = 16; o; o >>= 1) pv += __shfl_down_sync(0xffffffffu, pv, o);
        if ((tid & 31) == 0) s_par[tid >> 5] = pv;
    }
    __syncthreads();
    if (tid == 0) s_pref = s_par[0] + s_par[1];
    __syncthreads();
    int pref = s_pref;

    if (i < N_NODES) {
        int r = excl + pref;
        g_rowstart[i] = r;
        g_fill[i] = r;
        g_dinv[i] = rsqrtf((float)d + 1.0f);
    }
    if (i == 0) g_rowstart[N_NODES] = N_EDGES;
}

// ---------------- fused: CSR fill + pre-scaled fp16 x rows (known good) ----------------
__global__ void k_fill_prescale(const int* __restrict__ ei, const float* __restrict__ x) {
    int b = blockIdx.x, tid = threadIdx.x;
    if (b < CD_BLOCKS) {
        int i = b * 256 + tid;
        if (i < N_EDGES) {
            int src = ei[i];
            int dst = ei[N_EDGES + i];
            int pos = atomicAdd(&g_fill[dst], 1);
            g_csr[pos] = src;
        }
    } else {
        int idx = (b - CD_BLOCKS) * 256 + tid;
        if (idx >= N_NODES * 32) return;
        int row = idx >> 5;
        float dn = g_dinv[row];
        float4 v = *(const float4*)(x + (size_t)idx * 4);
        uint2 o;
        *(__half2*)&o.x = __floats2half2_rn(dn * v.x, dn * v.y);
        *(__half2*)&o.y = __floats2half2_rn(dn * v.z, dn * v.w);
        *(uint2*)(g_xs16 + (size_t)idx * 4) = o;
    }
}

// ---------------- layer-1 aggregation: unweighted fp16 sum -> fp16 out ----------------
// t1[n] = fp16( dinv[n] * ( xs[n] + sum_{s} xs[s] ) )
__global__ void __launch_bounds__(256) k_agg1(
    const __half* __restrict__ xs, __half* __restrict__ t1)
{
    int n = (blockIdx.x * blockDim.x + threadIdx.x) >> 5;
    if (n >= N_NODES) return;
    int lane = threadIdx.x & 31;
    int start = g_rowstart[n];
    int end   = g_rowstart[n + 1];
    float dn = g_dinv[n];

    uint2 raw = *(const uint2*)(xs + (size_t)n * 128 + lane * 4);
    float2 s01 = __half22float2(*(__half2*)&raw.x);
    float2 s23 = __half22float2(*(__half2*)&raw.y);
    float4 acc = make_float4(s01.x, s01.y, s23.x, s23.y);

    for (int r = start; r < end; r += 32) {
        int ne = min(32, end - r);
        int s = 0;
        if (lane < ne) s = g_csr[r + lane];
        int j = 0;
        for (; j + 4 <= ne; j += 4) {
            int s0 = __shfl_sync(0xffffffffu, s, j);
            int s1 = __shfl_sync(0xffffffffu, s, j + 1);
            int s2 = __shfl_sync(0xffffffffu, s, j + 2);
            int s3 = __shfl_sync(0xffffffffu, s, j + 3);
            uint2 r0 = *(const uint2*)(xs + (size_t)s0 * 128 + lane * 4);
            uint2 r1 = *(const uint2*)(xs + (size_t)s1 * 128 + lane * 4);
            uint2 r2 = *(const uint2*)(xs + (size_t)s2 * 128 + lane * 4);
            uint2 r3 = *(const uint2*)(xs + (size_t)s3 * 128 + lane * 4);
            float2 a0 = __half22float2(*(__half2*)&r0.x), b0 = __half22float2(*(__half2*)&r0.y);
            float2 a1 = __half22float2(*(__half2*)&r1.x), b1 = __half22float2(*(__half2*)&r1.y);
            float2 a2 = __half22float2(*(__half2*)&r2.x), b2 = __half22float2(*(__half2*)&r2.y);
            float2 a3 = __half22float2(*(__half2*)&r3.x), b3 = __half22float2(*(__half2*)&r3.y);
            acc.x += a0.x + a1.x; acc.y += a0.y + a1.y;
            acc.z += b0.x + b1.x; acc.w += b0.y + b1.y;
            acc.x += a2.x + a3.x; acc.y += a2.y + a3.y;
            acc.z += b2.x + b3.x; acc.w += b2.y + b3.y;
        }
        for (; j < ne; j++) {
            int sj = __shfl_sync(0xffffffffu, s, j);
            uint2 rv = *(const uint2*)(xs + (size_t)sj * 128 + lane * 4);
            float2 v01 = __half22float2(*(__half2*)&rv.x);
            float2 v23 = __half22float2(*(__half2*)&rv.y);
            acc.x += v01.x; acc.y += v01.y;
            acc.z += v23.x; acc.w += v23.y;
        }
    }
    uint2 o;
    *(__half2*)&o.x = __floats2half2_rn(dn * acc.x, dn * acc.y);
    *(__half2*)&o.y = __floats2half2_rn(dn * acc.z, dn * acc.w);
    *(uint2*)(t1 + (size_t)n * 128 + lane * 4) = o;
}

// ---------------- final aggregation: unweighted fp16 sum -> fp32 out + bias (known good) ----------------
__global__ void __launch_bounds__(256) k_agg2(
    const __half* __restrict__ ps, float* __restrict__ outp,
    const float* __restrict__ bias)
{
    int n = (blockIdx.x * blockDim.x + threadIdx.x) >> 5;
    if (n >= N_NODES) return;
    int lane = threadIdx.x & 31;
    int start = g_rowstart[n];
    int end   = g_rowstart[n + 1];
    float dn = g_dinv[n];

    uint2 raw = *(const uint2*)(ps + (size_t)n * 128 + lane * 4);
    float2 s01 = __half22float2(*(__half2*)&raw.x);
    float2 s23 = __half22float2(*(__half2*)&raw.y);
    float4 acc = make_float4(s01.x, s01.y, s23.x, s23.y);

    for (int r = start; r < end; r += 32) {
        int ne = min(32, end - r);
        int s = 0;
        if (lane < ne) s = g_csr[r + lane];
        int j = 0;
        for (; j + 4 <= ne; j += 4) {
            int s0 = __shfl_sync(0xffffffffu, s, j);
            int s1 = __shfl_sync(0xffffffffu, s, j + 1);
            int s2 = __shfl_sync(0xffffffffu, s, j + 2);
            int s3 = __shfl_sync(0xffffffffu, s, j + 3);
            uint2 r0 = *(const uint2*)(ps + (size_t)s0 * 128 + lane * 4);
            uint2 r1 = *(const uint2*)(ps + (size_t)s1 * 128 + lane * 4);
            uint2 r2 = *(const uint2*)(ps + (size_t)s2 * 128 + lane * 4);
            uint2 r3 = *(const uint2*)(ps + (size_t)s3 * 128 + lane * 4);
            float2 a0 = __half22float2(*(__half2*)&r0.x), b0 = __half22float2(*(__half2*)&r0.y);
            float2 a1 = __half22float2(*(__half2*)&r1.x), b1 = __half22float2(*(__half2*)&r1.y);
            float2 a2 = __half22float2(*(__half2*)&r2.x), b2 = __half22float2(*(__half2*)&r2.y);
            float2 a3 = __half22float2(*(__half2*)&r3.x), b3 = __half22float2(*(__half2*)&r3.y);
            acc.x += a0.x + a1.x; acc.y += a0.y + a1.y;
            acc.z += b0.x + b1.x; acc.w += b0.y + b1.y;
            acc.x += a2.x + a3.x; acc.y += a2.y + a3.y;
            acc.z += b2.x + b3.x; acc.w += b2.y + b3.y;
        }
        for (; j < ne; j++) {
            int sj = __shfl_sync(0xffffffffu, s, j);
            uint2 rv = *(const uint2*)(ps + (size_t)sj * 128 + lane * 4);
            float2 v01 = __half22float2(*(__half2*)&rv.x);
            float2 v23 = __half22float2(*(__half2*)&rv.y);
            acc.x += v01.x; acc.y += v01.y;
            acc.z += v23.x; acc.w += v23.y;
        }
    }
    float4 b = *(const float4*)(bias + lane * 4);
    float4 o;
    o.x = fmaf(dn, acc.x, b.x);
    o.y = fmaf(dn, acc.y, b.y);
    o.z = fmaf(dn, acc.z, b.z);
    o.w = fmaf(dn, acc.w, b.w);
    *(float4*)(outp + (size_t)n * 128 + lane * 4) = o;
}

// ---------------- fp16 mma.sync GEMM with cp.async 2-stage pipeline ----------------
// C[M,N] = A[M,K] @ Wt[N,K]^T, fp16 operands, fp32 accum, fp16 out.
// SCALEOUT: multiply output row by g_dinv[row] before store.
template<int N, int K, bool RELU, bool BIAS, bool SCALEOUT>
__global__ void __launch_bounds__(256) k_mma(
    const __half* __restrict__ A, const __half* __restrict__ Wt,
    const float* __restrict__ bias, __half* __restrict__ C, int M)
{
    constexpr int STG = 20480;            // bytes per stage (A 10240 + W 10240)
    constexpr int O_A = 0, O_W = 10240;
    constexpr int NK = K / 32;

    extern __shared__ __align__(16) char smem[];
    uint32_t su = smem_u32(smem);

    int tid = threadIdx.x, lane = tid & 31, wid = tid >> 5;
    int wm = wid >> 1, wn = wid & 1;
    int bm = blockIdx.x * 128, bn = blockIdx.y * 128;

    float acc[2][8][4];
    #pragma unroll
    for (int s = 0; s < 2; s++)
        #pragma unroll
        for (int p = 0; p < 8; p++)
            #pragma unroll
            for (int q = 0; q < 4; q++) acc[s][p][q] = 0.f;

    int a_r    = lane & 15;
    int a_half = lane >> 4;
    int b_nr   = ((lane >> 4) << 3) + (lane & 7);
    int b_half = (lane >> 3) & 1;

    auto load_stage = [&](int st, int k0) {
        uint32_t base = su + st * STG;
        #pragma unroll
        for (int ii = 0; ii < 2; ii++) {
            int i = tid + ii * 256;               // 512 chunks per array
            int row = i >> 2, c = i & 3;
            uint32_t soff = (uint32_t)row * 80 + c * 16;
            int grow = bm + row;
            uint32_t pA = (grow < M) ? 16u : 0u;
            int crow = grow < M ? grow : (M - 1);
            cpa16(base + O_A + soff, A + (size_t)crow * K + k0 + c * 8, pA);
            int nrow = bn + row;
            cpa16(base + O_W + soff, Wt + (size_t)nrow * K + k0 + c * 8, 16u);
        }
        cpa_commit();
    };

    load_stage(0, 0);

    for (int k0i = 0; k0i < NK; k0i++) {
        int buf = k0i & 1;
        if (k0i + 1 < NK) {
            load_stage(buf ^ 1, (k0i + 1) * 32);
            cpa_wait<1>();
        } else {
            cpa_wait<0>();
        }
        __syncthreads();

        uint32_t bA = su + buf * STG;
        #pragma unroll
        for (int kk = 0; kk < 32; kk += 16) {
            uint32_t ah[2][4];
            #pragma unroll
            for (int s = 0; s < 2; s++) {
                int row = wm * 32 + s * 16 + a_r;
                int kc = (kk >> 3) + a_half;
                uint32_t off = (uint32_t)row * 80 + kc * 16;
                ldsm4(ah[s], bA + O_A + off);
            }
            uint32_t bh[4][4];
            #pragma unroll
            for (int p = 0; p < 4; p++) {
                int row = wn * 64 + p * 16 + b_nr;
                int kc = (kk >> 3) + b_half;
                uint32_t off = (uint32_t)row * 80 + kc * 16;
                ldsm4(bh[p], bA + O_W + off);
            }
            #pragma unroll
            for (int s = 0; s < 2; s++)
                #pragma unroll
                for (int p = 0; p < 4; p++)
                    #pragma unroll
                    for (int t = 0; t < 2; t++)
                        mma16816h(acc[s][p * 2 + t], ah[s], bh[p][t * 2], bh[p][t * 2 + 1]);
        }
        __syncthreads();
    }

    // ---- epilogue: fp16 out ----
    int g = lane >> 2, t = lane & 3;
    #pragma unroll
    for (int s = 0; s < 2; s++) {
        int r0 = bm + wm * 32 + s * 16 + g;
        #pragma unroll
        for (int p8 = 0; p8 < 8; p8++) {
            int col = bn + wn * 64 + p8 * 8 + t * 2;
            float v0 = acc[s][p8][0], v1 = acc[s][p8][1];
            float v2 = acc[s][p8][2], v3 = acc[s][p8][3];
            if (BIAS) {
                float b0 = bias[col], b1 = bias[col + 1];
                v0 += b0; v1 += b1; v2 += b0; v3 += b1;
            }
            if (RELU) {
                v0 = fmaxf(v0, 0.f); v1 = fmaxf(v1, 0.f);
                v2 = fmaxf(v2, 0.f); v3 = fmaxf(v3, 0.f);
            }
            if (r0 < M) {
                float d0 = SCALEOUT ? g_dinv[r0] : 1.f;
                *(__half2*)(C + (size_t)r0 * N + col) = __floats2half2_rn(v0 * d0, v1 * d0);
            }
            if (r0 + 8 < M) {
                float d1 = SCALEOUT ? g_dinv[r0 + 8] : 1.f;
                *(__half2*)(C + (size_t)(r0 + 8) * N + col) = __floats2half2_rn(v2 * d1, v3 * d1);
            }
        }
    }
}

// ---------------- launch ----------------
extern "C" void kernel_launch(void* const* d_in, const int* in_sizes, int n_in,
                              void* d_out, int out_size)
{
    const float* x  = (const float*)d_in[0];
    const int*   ei = (const int*)  d_in[1];
    const float* W1 = (const float*)d_in[2];
    const float* b1 = (const float*)d_in[3];
    const float* W2 = (const float*)d_in[4];
    const float* b2 = (const float*)d_in[5];
    float* out = (float*)d_out;

    void *p_deg, *p_xs, *p_t1, *p_h, *p_ps, *p_w1, *p_w2;
    cudaGetSymbolAddress(&p_deg, g_deg);
    cudaGetSymbolAddress(&p_xs,  g_xs16);
    cudaGetSymbolAddress(&p_t1,  g_t1);
    cudaGetSymbolAddress(&p_h,   g_h);
    cudaGetSymbolAddress(&p_ps,  g_ps16);
    cudaGetSymbolAddress(&p_w1,  g_w1);
    cudaGetSymbolAddress(&p_w2,  g_w2);

    const int T = 256;
    const int SMEM_SZ = 40960;

    cudaFuncSetAttribute(k_mma<HID_CH, IN_CH, true, true, false>,
                         cudaFuncAttributeMaxDynamicSharedMemorySize, SMEM_SZ);
    cudaFuncSetAttribute(k_mma<OUT_CH, HID_CH, false, false, true>,
                         cudaFuncAttributeMaxDynamicSharedMemorySize, SMEM_SZ);

    // CSR build + weight prep + prescale
    cudaMemsetAsync(p_deg, 0, N_NODES * sizeof(int));
    k_count_prep<<<CD_BLOCKS + PW_BLOCKS, T>>>(ei, W1, W2);
    k_scan_fused<<<SCAN_NB, SCAN_BLK>>>();
    k_fill_prescale<<<CD_BLOCKS + PS_BLOCKS, T>>>(ei, x);

    int agrid = (N_NODES * 32 + T - 1) / T;   // one warp per node
    int mgrid = (N_NODES + 127) / 128;        // 391 M-blocks

    // ---- layer 1: unweighted gather of pre-scaled fp16 x, then fp16 tensor GEMM ----
    k_agg1<<<agrid, T>>>((const __half*)p_xs, (__half*)p_t1);
    {
        dim3 grid(mgrid, HID_CH / 128);
        k_mma<HID_CH, IN_CH, true, true, false><<<grid, 256, SMEM_SZ>>>(
            (const __half*)p_t1, (const __half*)p_w1, b1, (__half*)p_h, N_NODES);
    }

    // ---- layer 2: fp16 tensor GEMM (out pre-scaled by dinv), then unweighted gather ----
    {
        dim3 grid(mgrid, OUT_CH / 128);
        k_mma<OUT_CH, HID_CH, false, false, true><<<grid, 256, SMEM_SZ>>>(
            (const __half*)p_h, (const __half*)p_w2, nullptr, (__half*)p_ps, N_NODES);
    }
    k_agg2<<<agrid, T>>>((const __half*)p_ps, out, b2);
}